// round 14
// baseline (speedup 1.0000x reference)
#include <cuda_runtime.h>
#include <cuda_bf16.h>
#include <cuda_fp8.h>
#include <math.h>
#include <stdint.h>

#define N_BATCH 4
#define SEQ     4096
#define HID     1024
#define NHEADS  16
#define MROWS   (N_BATCH * SEQ)   // 16384

#define RSCALE 4096.0f
#define RISCALE (1.0f / 4096.0f)

// ---------------- scratch (device globals: no allocation allowed) ----------
__device__ __nv_bfloat16  g_xh  [MROWS * HID];
__device__ uint8_t        g_xh8 [MROWS * HID];
__device__ uint8_t        g_xl8 [MROWS * HID];
__device__ __nv_bfloat16  g_xTh [MROWS * HID];
__device__ __nv_bfloat16  g_xTl [MROWS * HID];
__device__ __nv_bfloat16  g_Gh  [N_BATCH * HID * HID];
__device__ __nv_bfloat16  g_Gl  [N_BATCH * HID * HID];
__device__ __nv_bfloat16  g_Ah  [MROWS * HID];   // permuted V, bf16 hi
__device__ uint8_t        g_A8h [MROWS * HID];   // permuted V, e4m3 hi
__device__ uint8_t        g_A8l [MROWS * HID];   // permuted V, e4m3 lo*4096
__device__ __nv_bfloat16  g_Wkh [HID * HID];
__device__ __nv_bfloat16  g_Wkl [HID * HID];
__device__ __nv_bfloat16  g_Wvh [HID * HID];
__device__ uint8_t        g_Wv8h[HID * HID];
__device__ uint8_t        g_Wv8l[HID * HID];
__device__ __nv_bfloat16  g_Woh [HID * HID];
__device__ uint8_t        g_Wo8h[HID * HID];
__device__ uint8_t        g_Wo8l[HID * HID];
__device__ float          g_E [N_BATCH * NHEADS * NHEADS];
__device__ float          g_A [N_BATCH * NHEADS * NHEADS];

// ======================= PTX helpers (baseline ISA) =========================
__device__ __forceinline__ uint32_t smem_u32(const void* p) {
    uint32_t a;
    asm("{ .reg .u64 t; cvta.to.shared.u64 t, %1; cvt.u32.u64 %0, t; }" : "=r"(a) : "l"(p));
    return a;
}
#define SWZ128(o) ((o) ^ (((o) >> 3) & 0x70))
#define SWZ64(o)  ((o) ^ (((o) >> 3) & 0x30))

__device__ __forceinline__ void cp_async16(uint32_t dst, const void* src) {
    asm volatile("cp.async.cg.shared.global [%0], [%1], 16;" :: "r"(dst), "l"(src));
}
#define CP_COMMIT() asm volatile("cp.async.commit_group;" ::: "memory")
#define CP_WAIT(n)  asm volatile("cp.async.wait_group %0;" :: "n"(n) : "memory")

__device__ __forceinline__ void ldsm_x4(uint32_t* r, uint32_t addr) {
    asm volatile("ldmatrix.sync.aligned.m8n8.x4.shared.b16 {%0,%1,%2,%3}, [%4];"
        : "=r"(r[0]), "=r"(r[1]), "=r"(r[2]), "=r"(r[3]) : "r"(addr));
}
__device__ __forceinline__ void mma_bf16(float* d, const uint32_t* a, const uint32_t* b) {
    asm volatile(
        "mma.sync.aligned.m16n8k16.row.col.f32.bf16.bf16.f32 "
        "{%0,%1,%2,%3}, {%4,%5,%6,%7}, {%8,%9}, {%0,%1,%2,%3};"
        : "+f"(d[0]), "+f"(d[1]), "+f"(d[2]), "+f"(d[3])
        : "r"(a[0]), "r"(a[1]), "r"(a[2]), "r"(a[3]), "r"(b[0]), "r"(b[1]));
}
__device__ __forceinline__ void mma_fp8(float* d, const uint32_t* a, const uint32_t* b) {
    asm volatile(
        "mma.sync.aligned.m16n8k32.row.col.f32.e4m3.e4m3.f32 "
        "{%0,%1,%2,%3}, {%4,%5,%6,%7}, {%8,%9}, {%0,%1,%2,%3};"
        : "+f"(d[0]), "+f"(d[1]), "+f"(d[2]), "+f"(d[3])
        : "r"(a[0]), "r"(a[1]), "r"(a[2]), "r"(a[3]), "r"(b[0]), "r"(b[1]));
}
__device__ __forceinline__ uint8_t f2e4m3(float v) {
    __nv_fp8_e4m3 t = __nv_fp8_e4m3(v);
    return *reinterpret_cast<uint8_t*>(&t);
}
__device__ __forceinline__ uint32_t pack2bf16(float a, float b) {
    __nv_bfloat162 t = __floats2bfloat162_rn(a, b);
    return *reinterpret_cast<uint32_t*>(&t);
}

// ======================= generic bf16x3 GEMM ================================
// mode 0: fp32 C out; mode 1: bf16 hi/lo out (+ symmetric mirror);
// mode 2: fused E-reduce: E[z,a,b] += sum_{i,d} Wq[i,a64+d]*Ctile[i,b64+d]
//         (no global C write)
#define STAGE3_BYTES 65536
#define GEMM3_SMEM   (3 * STAGE3_BYTES)
#define OFF_ES       67584     // after Cs (128*132*4)

__global__ __launch_bounds__(256, 1)
void gemm3(const __nv_bfloat16* __restrict__ Ah_, const __nv_bfloat16* __restrict__ Al_,
           const __nv_bfloat16* __restrict__ Bh_, const __nv_bfloat16* __restrict__ Bl_,
           int lda, int ldb, int K,
           size_t sA, size_t sB, size_t sC,
           float* __restrict__ Cf_,
           __nv_bfloat16* __restrict__ Ch_, __nv_bfloat16* __restrict__ Cl_,
           const float* __restrict__ Wq, float* __restrict__ Eg,
           int ldc, int mode, int symmetric)
{
    if (symmetric && (int)blockIdx.x < (int)blockIdx.y) return;
    extern __shared__ char smem[];
    const uint32_t sb = smem_u32(smem);
    const int tid  = threadIdx.x;
    const int wid  = tid >> 5, lane = tid & 31;
    const int wr   = wid >> 2, wc = wid & 3;
    const int z    = blockIdx.z;
    const int row0 = blockIdx.y * 128;
    const int col0 = blockIdx.x * 128;

    const __nv_bfloat16* base[4] = {
        Ah_ + (size_t)z * sA + (size_t)row0 * lda,
        Al_ + (size_t)z * sA + (size_t)row0 * lda,
        Bh_ + (size_t)z * sB + (size_t)col0 * ldb,
        Bl_ + (size_t)z * sB + (size_t)col0 * ldb };

    float acc[4][4][4];
#pragma unroll
    for (int mt = 0; mt < 4; mt++)
#pragma unroll
        for (int nt = 0; nt < 4; nt++)
#pragma unroll
            for (int e = 0; e < 4; e++) acc[mt][nt][e] = 0.0f;

    const int nst = K >> 6;

    auto issue = [&](int s) {
        const uint32_t st = sb + (s % 3) * STAGE3_BYTES;
        const int k0 = s * 64;
#pragma unroll
        for (int i = 0; i < 16; i++) {
            int c = tid + i * 256;
            int mat = c >> 10, j = c & 1023, row = j >> 3, q = j & 7;
            int ld = (mat < 2) ? lda : ldb;
            cp_async16(st + mat * 16384 + SWZ128((uint32_t)(row * 128 + q * 16)),
                       base[mat] + (size_t)row * ld + k0 + q * 8);
        }
        CP_COMMIT();
    };

    issue(0);
    issue(1);

    const int arow = wr * 64 + (lane & 15);
    const int brow = wc * 32 + (lane & 7) + ((lane >> 4) << 3);

    for (int s = 0; s < nst; s++) {
        if (s < nst - 1) CP_WAIT(1); else CP_WAIT(0);
        __syncthreads();
        if (s + 2 < nst) issue(s + 2);

        const uint32_t st = sb + (s % 3) * STAGE3_BYTES;
#pragma unroll
        for (int ks = 0; ks < 4; ks++) {
            uint32_t ah[4][4], al[4][4], bh[2][4], bl[2][4];
            const int abo = ks * 32 + (lane >> 4) * 16;
            const int bbo = ks * 32 + ((lane >> 3) & 1) * 16;
#pragma unroll
            for (int mt = 0; mt < 4; mt++) {
                uint32_t off = SWZ128((uint32_t)((arow + mt * 16) * 128 + abo));
                ldsm_x4(ah[mt], st + off);
                ldsm_x4(al[mt], st + 16384 + off);
            }
#pragma unroll
            for (int bt = 0; bt < 2; bt++) {
                uint32_t off = SWZ128((uint32_t)((brow + bt * 16) * 128 + bbo));
                ldsm_x4(bh[bt], st + 32768 + off);
                ldsm_x4(bl[bt], st + 49152 + off);
            }
#pragma unroll
            for (int mt = 0; mt < 4; mt++)
#pragma unroll
                for (int nt = 0; nt < 4; nt++) {
                    const uint32_t* bhp = &bh[nt >> 1][(nt & 1) * 2];
                    const uint32_t* blp = &bl[nt >> 1][(nt & 1) * 2];
                    mma_bf16(acc[mt][nt], ah[mt], bhp);
                    mma_bf16(acc[mt][nt], ah[mt], blp);
                    mma_bf16(acc[mt][nt], al[mt], bhp);
                }
        }
    }
    __syncthreads();

    float* Cs = reinterpret_cast<float*>(smem);   // [128][132]
    {
        const int r0 = wr * 64 + (lane >> 2);
        const int c0 = wc * 32 + (lane & 3) * 2;
#pragma unroll
        for (int mt = 0; mt < 4; mt++)
#pragma unroll
            for (int nt = 0; nt < 4; nt++) {
                int r = r0 + mt * 16, c = c0 + nt * 8;
                *reinterpret_cast<float2*>(&Cs[r * 132 + c]) =
                    make_float2(acc[mt][nt][0], acc[mt][nt][1]);
                *reinterpret_cast<float2*>(&Cs[(r + 8) * 132 + c]) =
                    make_float2(acc[mt][nt][2], acc[mt][nt][3]);
            }
    }
    __syncthreads();

    if (mode == 0) {
        float* C = Cf_ + (size_t)z * sC;
#pragma unroll
        for (int i = 0; i < 16; i++) {
            int idx = i * 256 + tid;
            int row = idx >> 5, q = idx & 31;
            float4 v = *reinterpret_cast<const float4*>(&Cs[row * 132 + q * 4]);
            *reinterpret_cast<float4*>(C + (size_t)(row0 + row) * ldc + col0 + q * 4) = v;
        }
    } else if (mode == 1) {
        __nv_bfloat16* Ch = Ch_ + (size_t)z * sC;
        __nv_bfloat16* Cl = Cl_ + (size_t)z * sC;
#pragma unroll
        for (int i = 0; i < 16; i++) {
            int idx = i * 256 + tid;
            int row = idx >> 5, q = idx & 31;
            float4 v = *reinterpret_cast<const float4*>(&Cs[row * 132 + q * 4]);
            float vv[4] = {v.x, v.y, v.z, v.w};
            float h0 = __bfloat162float(__float2bfloat16_rn(vv[0]));
            float h1 = __bfloat162float(__float2bfloat16_rn(vv[1]));
            float h2 = __bfloat162float(__float2bfloat16_rn(vv[2]));
            float h3 = __bfloat162float(__float2bfloat16_rn(vv[3]));
            uint2 hp = make_uint2(pack2bf16(vv[0], vv[1]), pack2bf16(vv[2], vv[3]));
            uint2 lp = make_uint2(pack2bf16(vv[0] - h0, vv[1] - h1),
                                  pack2bf16(vv[2] - h2, vv[3] - h3));
            size_t o = (size_t)(row0 + row) * ldc + col0 + q * 4;
            *reinterpret_cast<uint2*>(Ch + o) = hp;
            *reinterpret_cast<uint2*>(Cl + o) = lp;
        }
        if (symmetric && blockIdx.x != blockIdx.y) {
#pragma unroll
            for (int i = 0; i < 16; i++) {
                int idx = i * 256 + tid;
                int rp = idx >> 5, q = idx & 31;
                float vv[4];
#pragma unroll
                for (int e = 0; e < 4; e++) vv[e] = Cs[(q * 4 + e) * 132 + rp];
                float h0 = __bfloat162float(__float2bfloat16_rn(vv[0]));
                float h1 = __bfloat162float(__float2bfloat16_rn(vv[1]));
                float h2 = __bfloat162float(__float2bfloat16_rn(vv[2]));
                float h3 = __bfloat162float(__float2bfloat16_rn(vv[3]));
                uint2 hp = make_uint2(pack2bf16(vv[0], vv[1]), pack2bf16(vv[2], vv[3]));
                uint2 lp = make_uint2(pack2bf16(vv[0] - h0, vv[1] - h1),
                                      pack2bf16(vv[2] - h2, vv[3] - h3));
                size_t o = (size_t)(col0 + rp) * ldc + row0 + q * 4;
                *reinterpret_cast<uint2*>(Ch + o) = hp;
                *reinterpret_cast<uint2*>(Cl + o) = lp;
            }
        }
    } else {
        // mode 2: fused E reduction. Tile = T[row0+i][col0+c]; b = col0/64 + c/64.
        float* Es = reinterpret_cast<float*>(smem + OFF_ES);   // [32]: a*2+bl
        if (tid < 32) Es[tid] = 0.0f;
        __syncthreads();

        const int j    = tid & 127;       // tile col
        const int half = tid >> 7;        // row half 0/1
        const int d    = j & 63;
        const int bl   = j >> 6;
        const float* wqb = Wq + (size_t)(row0 + half * 64) * HID + d;

#pragma unroll 1
        for (int a = 0; a < 16; a++) {
            const float* wq = wqb + a * 64;
            float p = 0.0f;
#pragma unroll 8
            for (int r = 0; r < 64; r++)
                p = fmaf(wq[(size_t)r * HID], Cs[(half * 64 + r) * 132 + j], p);
            // warp reduce (all lanes in a warp share bl)
#pragma unroll
            for (int o = 16; o > 0; o >>= 1)
                p += __shfl_down_sync(0xFFFFFFFFu, p, o);
            if (lane == 0) atomicAdd(&Es[a * 2 + bl], p);
        }
        __syncthreads();
        if (tid < 32) {
            int a = tid >> 1, bl2 = tid & 1;
            atomicAdd(&Eg[z * 256 + a * 16 + (col0 >> 6) + bl2], Es[tid]);
        }
    }
}

// ======================= mixed bf16 + fp8 GEMM ==============================
// perm=0: C = A@B^T + bias (fp32 out)
// perm=1: write permuted attention operand (bf16-hi + e4m3 hi/lo)
// perm=2: fused attention mix epilogue
#define STAGE_BYTES 65536
#define NSTAGE      3
#define GEMM_SMEM   (NSTAGE * STAGE_BYTES)
#define OFF_AH   0
#define OFF_BH   16384
#define OFF_A8H  32768
#define OFF_A8L  40960
#define OFF_B8H  49152
#define OFF_B8L  57344
#define OFF_ATTN 67584     // after Cs (128*132*4 bytes)

__global__ __launch_bounds__(256, 1)
void gemm_mixed(const __nv_bfloat16* __restrict__ Agh,
                const uint8_t* __restrict__ Ag8h,
                const uint8_t* __restrict__ Ag8l,
                const __nv_bfloat16* __restrict__ Bgh,
                const uint8_t* __restrict__ Bg8h,
                const uint8_t* __restrict__ Bg8l,
                const float* __restrict__ bias,
                const float* __restrict__ attn,
                float* __restrict__ C,
                __nv_bfloat16* __restrict__ Ph,
                uint8_t* __restrict__ P8h,
                uint8_t* __restrict__ P8l,
                int perm)
{
    extern __shared__ char smem[];
    const uint32_t sb = smem_u32(smem);
    const int tid  = threadIdx.x;
    const int wid  = tid >> 5, lane = tid & 31;
    const int wr   = wid >> 2, wc = wid & 3;
    const int rowA0 = blockIdx.y * 128;
    const int rowB0 = blockIdx.x * 128;

    const __nv_bfloat16* pAh  = Agh  + (size_t)rowA0 * HID;
    const __nv_bfloat16* pBh  = Bgh  + (size_t)rowB0 * HID;
    const uint8_t*       pA8h = Ag8h + (size_t)rowA0 * HID;
    const uint8_t*       pA8l = Ag8l + (size_t)rowA0 * HID;
    const uint8_t*       pB8h = Bg8h + (size_t)rowB0 * HID;
    const uint8_t*       pB8l = Bg8l + (size_t)rowB0 * HID;

    float acc [4][4][4];
    float acc2[4][4][4];
#pragma unroll
    for (int mt = 0; mt < 4; mt++)
#pragma unroll
        for (int nt = 0; nt < 4; nt++)
#pragma unroll
            for (int e = 0; e < 4; e++) { acc[mt][nt][e] = 0.0f; acc2[mt][nt][e] = 0.0f; }

    auto issue = [&](int s) {
        const uint32_t st = sb + (s % NSTAGE) * STAGE_BYTES;
        const int k0 = s * 64;
#pragma unroll
        for (int i = 0; i < 16; i++) {
            int c = tid + i * 256;
            if (c < 2048) {
                int mat = c >> 10;
                int j = c & 1023, row = j >> 3, q = j & 7;
                const __nv_bfloat16* src = (mat ? pBh : pAh) + (size_t)row * HID + k0 + q * 8;
                cp_async16(st + mat * 16384 + SWZ128((uint32_t)(row * 128 + q * 16)), src);
            } else {
                int m2 = (c - 2048) >> 9;
                int j = c & 511, row = j >> 2, q = j & 3;
                const uint8_t* b8 = (m2 == 0) ? pA8h : (m2 == 1) ? pA8l
                                   : (m2 == 2) ? pB8h : pB8l;
                cp_async16(st + OFF_A8H + m2 * 8192 + SWZ64((uint32_t)(row * 64 + q * 16)),
                           b8 + (size_t)row * HID + k0 + q * 16);
            }
        }
        CP_COMMIT();
    };

    issue(0);
    issue(1);

    const int arow = wr * 64 + (lane & 15);
    const int brow = wc * 32 + (lane & 7) + ((lane >> 4) << 3);
    const int ar8  = wr * 64 + (lane & 7) + ((lane >> 3) & 1) * 8;
    const int akb  = ((lane >> 4) & 1) * 16;
    const int br8  = wc * 32 + (lane & 7) + ((lane >> 4) & 1) * 8;
    const int bkb  = ((lane >> 3) & 1) * 16;

    for (int s = 0; s < 16; s++) {
        if (s < 15) CP_WAIT(1); else CP_WAIT(0);
        __syncthreads();
        if (s + 2 < 16) issue(s + 2);

        const uint32_t st = sb + (s % NSTAGE) * STAGE_BYTES;
#pragma unroll
        for (int ks = 0; ks < 4; ks++) {
            uint32_t ah[4][4], bh[2][4];
            const int abo = ks * 32 + (lane >> 4) * 16;
            const int bbo = ks * 32 + ((lane >> 3) & 1) * 16;
#pragma unroll
            for (int mt = 0; mt < 4; mt++)
                ldsm_x4(ah[mt], st + OFF_AH + SWZ128((uint32_t)((arow + mt * 16) * 128 + abo)));
#pragma unroll
            for (int bt = 0; bt < 2; bt++)
                ldsm_x4(bh[bt], st + OFF_BH + SWZ128((uint32_t)((brow + bt * 16) * 128 + bbo)));
#pragma unroll
            for (int mt = 0; mt < 4; mt++)
#pragma unroll
                for (int nt = 0; nt < 4; nt++)
                    mma_bf16(acc[mt][nt], ah[mt], &bh[nt >> 1][(nt & 1) * 2]);
        }
#pragma unroll
        for (int kk = 0; kk < 2; kk++) {
            uint32_t a8h[4][4], a8l[4][4], b8h[2][4], b8l[2][4];
#pragma unroll
            for (int mt = 0; mt < 4; mt++) {
                uint32_t off = SWZ64((uint32_t)((ar8 + mt * 16) * 64 + kk * 32 + akb));
                ldsm_x4(a8h[mt], st + OFF_A8H + off);
                ldsm_x4(a8l[mt], st + OFF_A8L + off);
            }
#pragma unroll
            for (int bt = 0; bt < 2; bt++) {
                uint32_t off = SWZ64((uint32_t)((br8 + bt * 16) * 64 + kk * 32 + bkb));
                ldsm_x4(b8h[bt], st + OFF_B8H + off);
                ldsm_x4(b8l[bt], st + OFF_B8L + off);
            }
#pragma unroll
            for (int mt = 0; mt < 4; mt++)
#pragma unroll
                for (int nt = 0; nt < 4; nt++) {
                    mma_fp8(acc2[mt][nt], a8l[mt], &b8h[nt >> 1][(nt & 1) * 2]);
                    mma_fp8(acc2[mt][nt], a8h[mt], &b8l[nt >> 1][(nt & 1) * 2]);
                }
        }
    }
    __syncthreads();

    float* Cs = reinterpret_cast<float*>(smem);   // [128][132]
    float* at = reinterpret_cast<float*>(smem + OFF_ATTN);   // [256]
    {
        const int r0 = wr * 64 + (lane >> 2);
        const int c0 = wc * 32 + (lane & 3) * 2;
#pragma unroll
        for (int mt = 0; mt < 4; mt++)
#pragma unroll
            for (int nt = 0; nt < 4; nt++) {
                int r = r0 + mt * 16, c = c0 + nt * 8;
                float v0 = acc[mt][nt][0] + acc2[mt][nt][0] * RISCALE;
                float v1 = acc[mt][nt][1] + acc2[mt][nt][1] * RISCALE;
                float v2 = acc[mt][nt][2] + acc2[mt][nt][2] * RISCALE;
                float v3 = acc[mt][nt][3] + acc2[mt][nt][3] * RISCALE;
                *reinterpret_cast<float2*>(&Cs[r * 132 + c])       = make_float2(v0, v1);
                *reinterpret_cast<float2*>(&Cs[(r + 8) * 132 + c]) = make_float2(v2, v3);
            }
    }
    if (perm == 2) at[tid] = attn[(rowA0 >> 12) * 256 + tid];
    __syncthreads();

    if (perm == 0) {
#pragma unroll
        for (int i = 0; i < 16; i++) {
            int idx = i * 256 + tid;
            int row = idx >> 5, q = idx & 31;
            float4 v = *reinterpret_cast<const float4*>(&Cs[row * 132 + q * 4]);
            int colg = rowB0 + q * 4;
            if (bias) {
                float4 b = *reinterpret_cast<const float4*>(bias + colg);
                v.x += b.x; v.y += b.y; v.z += b.z; v.w += b.w;
            }
            *reinterpret_cast<float4*>(C + (size_t)(rowA0 + row) * HID + colg) = v;
        }
    } else if (perm == 1) {
#pragma unroll
        for (int i = 0; i < 16; i++) {
            int idx = i * 256 + tid;
            int row = idx >> 5, q = idx & 31;
            float4 v = *reinterpret_cast<const float4*>(&Cs[row * 132 + q * 4]);
            float vv[4] = {v.x, v.y, v.z, v.w};

            int m = rowA0 + row;
            int n = m >> 12;
            int s = m & 4095;
            int u = s >> 4, r = s & 15;
            int c = rowB0 + q * 4;
            int b = c >> 6, d = c & 63;
            size_t o = ((size_t)((n * 256 + u) * 16 + b)) * HID + r * 64 + d;

            float h0 = __bfloat162float(__float2bfloat16_rn(vv[0]));
            float h1 = __bfloat162float(__float2bfloat16_rn(vv[1]));
            float h2 = __bfloat162float(__float2bfloat16_rn(vv[2]));
            float h3 = __bfloat162float(__float2bfloat16_rn(vv[3]));
            uint2 hp = make_uint2(pack2bf16(vv[0], vv[1]), pack2bf16(vv[2], vv[3]));
            uint8_t h8[4] = { f2e4m3(vv[0]), f2e4m3(vv[1]), f2e4m3(vv[2]), f2e4m3(vv[3]) };
            uint8_t l8[4] = { f2e4m3((vv[0] - h0) * RSCALE), f2e4m3((vv[1] - h1) * RSCALE),
                              f2e4m3((vv[2] - h2) * RSCALE), f2e4m3((vv[3] - h3) * RSCALE) };
            *reinterpret_cast<uint2*>(Ph + o)     = hp;
            *reinterpret_cast<uint32_t*>(P8h + o) = *reinterpret_cast<uint32_t*>(h8);
            *reinterpret_cast<uint32_t*>(P8l + o) = *reinterpret_cast<uint32_t*>(l8);
        }
    } else {
        const int n  = rowA0 >> 12;
        const int u0 = (rowA0 & 4095) >> 4;
        const int g  = tid >> 5;
        const int q  = tid & 31;
        float4 bb = make_float4(0.f, 0.f, 0.f, 0.f);
        if (bias) bb = *reinterpret_cast<const float4*>(bias + rowB0 + q * 4);
#pragma unroll
        for (int a = 0; a < 16; a++) {
            float4 o4 = bb;
#pragma unroll
            for (int b = 0; b < 16; b++) {
                float w = at[a * 16 + b];
                const float* zr = &Cs[(g * 16 + b) * 132 + q * 4];
                o4.x = fmaf(w, zr[0], o4.x);
                o4.y = fmaf(w, zr[1], o4.y);
                o4.z = fmaf(w, zr[2], o4.z);
                o4.w = fmaf(w, zr[3], o4.w);
            }
            size_t orow = (size_t)n * SEQ + (size_t)a * 256 + (u0 + g);
            *reinterpret_cast<float4*>(C + orow * HID + rowB0 + q * 4) = o4;
        }
    }
}

// ============ x converts (vectorized) =======================================
__global__ __launch_bounds__(256)
void convert_x(const float* __restrict__ x)
{
    const int z  = blockIdx.z;
    const int s0 = blockIdx.y * 32;
    const int c0 = blockIdx.x * 128;
    __shared__ float tile[32][129];
    const float* xb = x + (size_t)z * SEQ * HID;

    const int r  = threadIdx.x >> 3;
    const int cc = (threadIdx.x & 7) * 16;
    float v[16];
    const float* src = xb + (size_t)(s0 + r) * HID + c0 + cc;
#pragma unroll
    for (int i = 0; i < 4; i++) {
        float4 f = *reinterpret_cast<const float4*>(src + i * 4);
        v[i * 4 + 0] = f.x; v[i * 4 + 1] = f.y;
        v[i * 4 + 2] = f.z; v[i * 4 + 3] = f.w;
    }
    __nv_bfloat16 h[16]; uint8_t h8[16], l8[16];
#pragma unroll
    for (int k = 0; k < 16; k++) {
        tile[r][cc + k] = v[k];
        h[k] = __float2bfloat16_rn(v[k]);
        float lo = v[k] - __bfloat162float(h[k]);
        h8[k] = f2e4m3(v[k]);
        l8[k] = f2e4m3(lo * RSCALE);
    }
    size_t o = ((size_t)z * SEQ + s0 + r) * HID + c0 + cc;
    *reinterpret_cast<uint4*>(g_xh + o)     = reinterpret_cast<uint4*>(h)[0];
    *reinterpret_cast<uint4*>(g_xh + o + 8) = reinterpret_cast<uint4*>(h)[1];
    *reinterpret_cast<uint4*>(g_xh8 + o)    = *reinterpret_cast<uint4*>(h8);
    *reinterpret_cast<uint4*>(g_xl8 + o)    = *reinterpret_cast<uint4*>(l8);
    __syncthreads();

    const int ch = threadIdx.x >> 1;
    const int sh = (threadIdx.x & 1) * 16;
    __nv_bfloat16 th[16], tl[16];
#pragma unroll
    for (int k = 0; k < 16; k++) {
        float vv = tile[sh + k][ch];
        __nv_bfloat16 hh = __float2bfloat16_rn(vv);
        th[k] = hh;
        tl[k] = __float2bfloat16_rn(vv - __bfloat162float(hh));
    }
    size_t ot = ((size_t)z * HID + c0 + ch) * SEQ + s0 + sh;
    *reinterpret_cast<uint4*>(g_xTh + ot)     = reinterpret_cast<uint4*>(th)[0];
    *reinterpret_cast<uint4*>(g_xTh + ot + 8) = reinterpret_cast<uint4*>(th)[1];
    *reinterpret_cast<uint4*>(g_xTl + ot)     = reinterpret_cast<uint4*>(tl)[0];
    *reinterpret_cast<uint4*>(g_xTl + ot + 8) = reinterpret_cast<uint4*>(tl)[1];
}

// ===== W converts ===========================================================
__global__ __launch_bounds__(256)
void convert_w(const float* __restrict__ Wk, const float* __restrict__ Wv,
               const float* __restrict__ Wo)
{
    const int z = blockIdx.z;
    const float* W = (z == 0) ? Wk : (z == 1) ? Wv : Wo;
    __shared__ float tile[32][33];
    const int tx = threadIdx.x & 31, ty = threadIdx.x >> 5;
    const int bx = blockIdx.x, by = blockIdx.y;
#pragma unroll
    for (int i = 0; i < 4; i++) {
        int kl = ty * 4 + i;
        tile[kl][tx] = W[(size_t)(by * 32 + kl) * HID + bx * 32 + tx];
    }
    __syncthreads();
#pragma unroll
    for (int i = 0; i < 4; i++) {
        int nl = ty * 4 + i;
        float v = tile[tx][nl];
        __nv_bfloat16 h = __float2bfloat16_rn(v);
        float lo = v - __bfloat162float(h);
        size_t o = (size_t)(bx * 32 + nl) * HID + by * 32 + tx;
        if (z == 0) {
            g_Wkh[o] = h;
            g_Wkl[o] = __float2bfloat16_rn(lo);
        } else if (z == 1) {
            g_Wvh[o] = h;
            g_Wv8h[o] = f2e4m3(v);
            g_Wv8l[o] = f2e4m3(lo * RSCALE);
        } else {
            g_Woh[o] = h;
            g_Wo8h[o] = f2e4m3(v);
            g_Wo8l[o] = f2e4m3(lo * RSCALE);
        }
    }
}

// ---------------- softmax over b ------------------------------------------
__global__ void softmax_kernel()
{
    int t = threadIdx.x;
    if (t >= N_BATCH * NHEADS) return;
    int n = t >> 4, a = t & 15;
    const float* e = g_E + n * 256 + a * 16;
    float v[16], m = -1e30f;
#pragma unroll
    for (int b = 0; b < 16; b++) { v[b] = e[b] * 0.125f; m = fmaxf(m, v[b]); }
    float s = 0.0f;
#pragma unroll
    for (int b = 0; b < 16; b++) { v[b] = expf(v[b] - m); s += v[b]; }
    float inv = 1.0f / s;
    float* o = g_A + n * 256 + a * 16;
#pragma unroll
    for (int b = 0; b < 16; b++) o[b] = v[b] * inv;
}

// ---------------- launch ----------------------------------------------------
extern "C" void kernel_launch(void* const* d_in, const int* in_sizes, int n_in,
                              void* d_out, int out_size)
{
    const float* x  = (const float*)d_in[0];
    const float* Wq = (const float*)d_in[1];
    const float* Wk = (const float*)d_in[2];
    const float* Wv = (const float*)d_in[3];
    const float* Wo = (const float*)d_in[4];
    const float* bo = (const float*)d_in[5];
    float* out = (float*)d_out;

    float *pE, *pAtn;
    __nv_bfloat16 *pxh, *pxTh, *pxTl, *pGh, *pGl, *pAh;
    __nv_bfloat16 *pWkh, *pWkl, *pWvh, *pWoh;
    uint8_t *pxh8, *pxl8, *pA8h, *pA8l, *pWv8h, *pWv8l, *pWo8h, *pWo8l;
    cudaGetSymbolAddress((void**)&pE,  g_E);
    cudaGetSymbolAddress((void**)&pAtn, g_A);
    cudaGetSymbolAddress((void**)&pxh, g_xh);
    cudaGetSymbolAddress((void**)&pxh8, g_xh8);
    cudaGetSymbolAddress((void**)&pxl8, g_xl8);
    cudaGetSymbolAddress((void**)&pxTh, g_xTh);
    cudaGetSymbolAddress((void**)&pxTl, g_xTl);
    cudaGetSymbolAddress((void**)&pGh, g_Gh);
    cudaGetSymbolAddress((void**)&pGl, g_Gl);
    cudaGetSymbolAddress((void**)&pAh, g_Ah);
    cudaGetSymbolAddress((void**)&pA8h, g_A8h);
    cudaGetSymbolAddress((void**)&pA8l, g_A8l);
    cudaGetSymbolAddress((void**)&pWkh, g_Wkh);
    cudaGetSymbolAddress((void**)&pWkl, g_Wkl);
    cudaGetSymbolAddress((void**)&pWvh, g_Wvh);
    cudaGetSymbolAddress((void**)&pWoh, g_Woh);
    cudaGetSymbolAddress((void**)&pWv8h, g_Wv8h);
    cudaGetSymbolAddress((void**)&pWv8l, g_Wv8l);
    cudaGetSymbolAddress((void**)&pWo8h, g_Wo8h);
    cudaGetSymbolAddress((void**)&pWo8l, g_Wo8l);

    cudaFuncSetAttribute(gemm3, cudaFuncAttributeMaxDynamicSharedMemorySize, GEMM3_SMEM);
    cudaFuncSetAttribute(gemm_mixed, cudaFuncAttributeMaxDynamicSharedMemorySize, GEMM_SMEM);

    convert_x<<<dim3(HID / 128, SEQ / 32, N_BATCH), 256>>>(x);
    convert_w<<<dim3(HID / 32, HID / 32, 3), 256>>>(Wk, Wv, Wo);

    // Gram: G[n] = x[n]^T x[n]  (bf16 hi/lo out, symmetric)
    gemm3<<<dim3(8, 8, N_BATCH), 256, GEMM3_SMEM>>>(
        pxTh, pxTl, pxTh, pxTl, SEQ, SEQ, SEQ,
        (size_t)HID * SEQ, (size_t)HID * SEQ, (size_t)HID * HID,
        nullptr, pGh, pGl, nullptr, nullptr, HID, 1, 1);

    // T = G @ Wk with fused E-reduction (no T materialization)
    cudaMemsetAsync(pE, 0, N_BATCH * NHEADS * NHEADS * sizeof(float), 0);
    gemm3<<<dim3(8, 8, N_BATCH), 256, GEMM3_SMEM>>>(
        pGh, pGl, pWkh, pWkl, HID, HID, HID,
        (size_t)HID * HID, 0, 0,
        nullptr, nullptr, nullptr, Wq, pE, HID, 2, 0);

    softmax_kernel<<<1, 64>>>();

    // V = x @ Wv, epilogue writes permuted split operand A
    gemm_mixed<<<dim3(HID / 128, MROWS / 128), 256, GEMM_SMEM>>>(
        pxh, pxh8, pxl8, pWvh, pWv8h, pWv8l, nullptr, nullptr,
        nullptr, pAh, pA8h, pA8l, 1);

    // out = attn-mix(A @ Wo) + bo, fused epilogue
    gemm_mixed<<<dim3(HID / 128, MROWS / 128), 256, GEMM_SMEM>>>(
        pAh, pA8h, pA8l, pWoh, pWo8h, pWo8l, bo, pAtn,
        out, nullptr, nullptr, nullptr, 2);
}

// round 15
// speedup vs baseline: 1.0484x; 1.0484x over previous
#include <cuda_runtime.h>
#include <cuda_bf16.h>
#include <cuda_fp8.h>
#include <math.h>
#include <stdint.h>

#define N_BATCH 4
#define SEQ     4096
#define HID     1024
#define NHEADS  16
#define MROWS   (N_BATCH * SEQ)   // 16384

#define RSCALE 4096.0f
#define RISCALE (1.0f / 4096.0f)

// ---------------- scratch (device globals: no allocation allowed) ----------
__device__ __nv_bfloat16  g_xh  [MROWS * HID];
__device__ uint8_t        g_xh8 [MROWS * HID];
__device__ uint8_t        g_xl8 [MROWS * HID];
__device__ __nv_bfloat16  g_xTh [MROWS * HID];
__device__ __nv_bfloat16  g_xTl [MROWS * HID];
__device__ __nv_bfloat16  g_Gh  [N_BATCH * HID * HID];
__device__ __nv_bfloat16  g_Gl  [N_BATCH * HID * HID];
__device__ float          g_T   [N_BATCH * HID * HID];
__device__ __nv_bfloat16  g_Ah  [MROWS * HID];   // permuted V, bf16 hi
__device__ uint8_t        g_A8h [MROWS * HID];   // permuted V, e4m3 hi
__device__ uint8_t        g_A8l [MROWS * HID];   // permuted V, e4m3 lo*4096
__device__ __nv_bfloat16  g_Wkh [HID * HID];
__device__ __nv_bfloat16  g_Wkl [HID * HID];
__device__ __nv_bfloat16  g_Wvh [HID * HID];
__device__ uint8_t        g_Wv8h[HID * HID];
__device__ uint8_t        g_Wv8l[HID * HID];
__device__ __nv_bfloat16  g_Woh [HID * HID];
__device__ uint8_t        g_Wo8h[HID * HID];
__device__ uint8_t        g_Wo8l[HID * HID];
__device__ float          g_Ep [N_BATCH * 64 * 256];   // E partials per (n, i0)
__device__ float          g_A [N_BATCH * NHEADS * NHEADS];

// ======================= PTX helpers (baseline ISA) =========================
__device__ __forceinline__ uint32_t smem_u32(const void* p) {
    uint32_t a;
    asm("{ .reg .u64 t; cvta.to.shared.u64 t, %1; cvt.u32.u64 %0, t; }" : "=r"(a) : "l"(p));
    return a;
}
#define SWZ128(o) ((o) ^ (((o) >> 3) & 0x70))
#define SWZ64(o)  ((o) ^ (((o) >> 3) & 0x30))

__device__ __forceinline__ void cp_async16(uint32_t dst, const void* src) {
    asm volatile("cp.async.cg.shared.global [%0], [%1], 16;" :: "r"(dst), "l"(src));
}
#define CP_COMMIT() asm volatile("cp.async.commit_group;" ::: "memory")
#define CP_WAIT(n)  asm volatile("cp.async.wait_group %0;" :: "n"(n) : "memory")

__device__ __forceinline__ void ldsm_x4(uint32_t* r, uint32_t addr) {
    asm volatile("ldmatrix.sync.aligned.m8n8.x4.shared.b16 {%0,%1,%2,%3}, [%4];"
        : "=r"(r[0]), "=r"(r[1]), "=r"(r[2]), "=r"(r[3]) : "r"(addr));
}
__device__ __forceinline__ void mma_bf16(float* d, const uint32_t* a, const uint32_t* b) {
    asm volatile(
        "mma.sync.aligned.m16n8k16.row.col.f32.bf16.bf16.f32 "
        "{%0,%1,%2,%3}, {%4,%5,%6,%7}, {%8,%9}, {%0,%1,%2,%3};"
        : "+f"(d[0]), "+f"(d[1]), "+f"(d[2]), "+f"(d[3])
        : "r"(a[0]), "r"(a[1]), "r"(a[2]), "r"(a[3]), "r"(b[0]), "r"(b[1]));
}
__device__ __forceinline__ void mma_fp8(float* d, const uint32_t* a, const uint32_t* b) {
    asm volatile(
        "mma.sync.aligned.m16n8k32.row.col.f32.e4m3.e4m3.f32 "
        "{%0,%1,%2,%3}, {%4,%5,%6,%7}, {%8,%9}, {%0,%1,%2,%3};"
        : "+f"(d[0]), "+f"(d[1]), "+f"(d[2]), "+f"(d[3])
        : "r"(a[0]), "r"(a[1]), "r"(a[2]), "r"(a[3]), "r"(b[0]), "r"(b[1]));
}
__device__ __forceinline__ uint8_t f2e4m3(float v) {
    __nv_fp8_e4m3 t = __nv_fp8_e4m3(v);
    return *reinterpret_cast<uint8_t*>(&t);
}
__device__ __forceinline__ uint32_t pack2bf16(float a, float b) {
    __nv_bfloat162 t = __floats2bfloat162_rn(a, b);
    return *reinterpret_cast<uint32_t*>(&t);
}

// ======================= generic bf16x3 GEMM (champion) =====================
#define STAGE3_BYTES 65536
#define GEMM3_SMEM   (3 * STAGE3_BYTES)

__global__ __launch_bounds__(256, 1)
void gemm3(const __nv_bfloat16* __restrict__ Ah_, const __nv_bfloat16* __restrict__ Al_,
           const __nv_bfloat16* __restrict__ Bh_, const __nv_bfloat16* __restrict__ Bl_,
           int lda, int ldb, int K,
           size_t sA, size_t sB, size_t sC,
           float* __restrict__ Cf_,
           __nv_bfloat16* __restrict__ Ch_, __nv_bfloat16* __restrict__ Cl_,
           int ldc, int mode, int symmetric)
{
    if (symmetric && (int)blockIdx.x < (int)blockIdx.y) return;
    extern __shared__ char smem[];
    const uint32_t sb = smem_u32(smem);
    const int tid  = threadIdx.x;
    const int wid  = tid >> 5, lane = tid & 31;
    const int wr   = wid >> 2, wc = wid & 3;
    const int z    = blockIdx.z;
    const int row0 = blockIdx.y * 128;
    const int col0 = blockIdx.x * 128;

    const __nv_bfloat16* base[4] = {
        Ah_ + (size_t)z * sA + (size_t)row0 * lda,
        Al_ + (size_t)z * sA + (size_t)row0 * lda,
        Bh_ + (size_t)z * sB + (size_t)col0 * ldb,
        Bl_ + (size_t)z * sB + (size_t)col0 * ldb };

    float acc[4][4][4];
#pragma unroll
    for (int mt = 0; mt < 4; mt++)
#pragma unroll
        for (int nt = 0; nt < 4; nt++)
#pragma unroll
            for (int e = 0; e < 4; e++) acc[mt][nt][e] = 0.0f;

    const int nst = K >> 6;

    auto issue = [&](int s) {
        const uint32_t st = sb + (s % 3) * STAGE3_BYTES;
        const int k0 = s * 64;
#pragma unroll
        for (int i = 0; i < 16; i++) {
            int c = tid + i * 256;
            int mat = c >> 10, j = c & 1023, row = j >> 3, q = j & 7;
            int ld = (mat < 2) ? lda : ldb;
            cp_async16(st + mat * 16384 + SWZ128((uint32_t)(row * 128 + q * 16)),
                       base[mat] + (size_t)row * ld + k0 + q * 8);
        }
        CP_COMMIT();
    };

    issue(0);
    issue(1);

    const int arow = wr * 64 + (lane & 15);
    const int brow = wc * 32 + (lane & 7) + ((lane >> 4) << 3);

    for (int s = 0; s < nst; s++) {
        if (s < nst - 1) CP_WAIT(1); else CP_WAIT(0);
        __syncthreads();
        if (s + 2 < nst) issue(s + 2);

        const uint32_t st = sb + (s % 3) * STAGE3_BYTES;
#pragma unroll
        for (int ks = 0; ks < 4; ks++) {
            uint32_t ah[4][4], al[4][4], bh[2][4], bl[2][4];
            const int abo = ks * 32 + (lane >> 4) * 16;
            const int bbo = ks * 32 + ((lane >> 3) & 1) * 16;
#pragma unroll
            for (int mt = 0; mt < 4; mt++) {
                uint32_t off = SWZ128((uint32_t)((arow + mt * 16) * 128 + abo));
                ldsm_x4(ah[mt], st + off);
                ldsm_x4(al[mt], st + 16384 + off);
            }
#pragma unroll
            for (int bt = 0; bt < 2; bt++) {
                uint32_t off = SWZ128((uint32_t)((brow + bt * 16) * 128 + bbo));
                ldsm_x4(bh[bt], st + 32768 + off);
                ldsm_x4(bl[bt], st + 49152 + off);
            }
#pragma unroll
            for (int mt = 0; mt < 4; mt++)
#pragma unroll
                for (int nt = 0; nt < 4; nt++) {
                    const uint32_t* bhp = &bh[nt >> 1][(nt & 1) * 2];
                    const uint32_t* blp = &bl[nt >> 1][(nt & 1) * 2];
                    mma_bf16(acc[mt][nt], ah[mt], bhp);
                    mma_bf16(acc[mt][nt], ah[mt], blp);
                    mma_bf16(acc[mt][nt], al[mt], bhp);
                }
        }
    }
    __syncthreads();

    float* Cs = reinterpret_cast<float*>(smem);   // [128][132]
    {
        const int r0 = wr * 64 + (lane >> 2);
        const int c0 = wc * 32 + (lane & 3) * 2;
#pragma unroll
        for (int mt = 0; mt < 4; mt++)
#pragma unroll
            for (int nt = 0; nt < 4; nt++) {
                int r = r0 + mt * 16, c = c0 + nt * 8;
                *reinterpret_cast<float2*>(&Cs[r * 132 + c]) =
                    make_float2(acc[mt][nt][0], acc[mt][nt][1]);
                *reinterpret_cast<float2*>(&Cs[(r + 8) * 132 + c]) =
                    make_float2(acc[mt][nt][2], acc[mt][nt][3]);
            }
    }
    __syncthreads();

    if (mode == 0) {
        float* C = Cf_ + (size_t)z * sC;
#pragma unroll
        for (int i = 0; i < 16; i++) {
            int idx = i * 256 + tid;
            int row = idx >> 5, q = idx & 31;
            float4 v = *reinterpret_cast<const float4*>(&Cs[row * 132 + q * 4]);
            *reinterpret_cast<float4*>(C + (size_t)(row0 + row) * ldc + col0 + q * 4) = v;
        }
    } else {
        __nv_bfloat16* Ch = Ch_ + (size_t)z * sC;
        __nv_bfloat16* Cl = Cl_ + (size_t)z * sC;
#pragma unroll
        for (int i = 0; i < 16; i++) {
            int idx = i * 256 + tid;
            int row = idx >> 5, q = idx & 31;
            float4 v = *reinterpret_cast<const float4*>(&Cs[row * 132 + q * 4]);
            float vv[4] = {v.x, v.y, v.z, v.w};
            float h0 = __bfloat162float(__float2bfloat16_rn(vv[0]));
            float h1 = __bfloat162float(__float2bfloat16_rn(vv[1]));
            float h2 = __bfloat162float(__float2bfloat16_rn(vv[2]));
            float h3 = __bfloat162float(__float2bfloat16_rn(vv[3]));
            uint2 hp = make_uint2(pack2bf16(vv[0], vv[1]), pack2bf16(vv[2], vv[3]));
            uint2 lp = make_uint2(pack2bf16(vv[0] - h0, vv[1] - h1),
                                  pack2bf16(vv[2] - h2, vv[3] - h3));
            size_t o = (size_t)(row0 + row) * ldc + col0 + q * 4;
            *reinterpret_cast<uint2*>(Ch + o) = hp;
            *reinterpret_cast<uint2*>(Cl + o) = lp;
        }
        if (symmetric && blockIdx.x != blockIdx.y) {
#pragma unroll
            for (int i = 0; i < 16; i++) {
                int idx = i * 256 + tid;
                int rp = idx >> 5, q = idx & 31;
                float vv[4];
#pragma unroll
                for (int e = 0; e < 4; e++) vv[e] = Cs[(q * 4 + e) * 132 + rp];
                float h0 = __bfloat162float(__float2bfloat16_rn(vv[0]));
                float h1 = __bfloat162float(__float2bfloat16_rn(vv[1]));
                float h2 = __bfloat162float(__float2bfloat16_rn(vv[2]));
                float h3 = __bfloat162float(__float2bfloat16_rn(vv[3]));
                uint2 hp = make_uint2(pack2bf16(vv[0], vv[1]), pack2bf16(vv[2], vv[3]));
                uint2 lp = make_uint2(pack2bf16(vv[0] - h0, vv[1] - h1),
                                      pack2bf16(vv[2] - h2, vv[3] - h3));
                size_t o = (size_t)(col0 + rp) * ldc + row0 + q * 4;
                *reinterpret_cast<uint2*>(Ch + o) = hp;
                *reinterpret_cast<uint2*>(Cl + o) = lp;
            }
        }
    }
}

// ======================= mixed bf16 + fp8 GEMM ==============================
// perm=0: C = A@B^T + bias (fp32 out)
// perm=1: write permuted attention operand (bf16-hi + e4m3 hi/lo)
// perm=2: fused attention mix epilogue
#define STAGE_BYTES 65536
#define NSTAGE      3
#define GEMM_SMEM   (NSTAGE * STAGE_BYTES)
#define OFF_AH   0
#define OFF_BH   16384
#define OFF_A8H  32768
#define OFF_A8L  40960
#define OFF_B8H  49152
#define OFF_B8L  57344
#define OFF_ATTN 67584     // after Cs (128*132*4 bytes)

__global__ __launch_bounds__(256, 1)
void gemm_mixed(const __nv_bfloat16* __restrict__ Agh,
                const uint8_t* __restrict__ Ag8h,
                const uint8_t* __restrict__ Ag8l,
                const __nv_bfloat16* __restrict__ Bgh,
                const uint8_t* __restrict__ Bg8h,
                const uint8_t* __restrict__ Bg8l,
                const float* __restrict__ bias,
                const float* __restrict__ attn,
                float* __restrict__ C,
                __nv_bfloat16* __restrict__ Ph,
                uint8_t* __restrict__ P8h,
                uint8_t* __restrict__ P8l,
                int perm)
{
    extern __shared__ char smem[];
    const uint32_t sb = smem_u32(smem);
    const int tid  = threadIdx.x;
    const int wid  = tid >> 5, lane = tid & 31;
    const int wr   = wid >> 2, wc = wid & 3;
    const int rowA0 = blockIdx.y * 128;
    const int rowB0 = blockIdx.x * 128;

    const __nv_bfloat16* pAh  = Agh  + (size_t)rowA0 * HID;
    const __nv_bfloat16* pBh  = Bgh  + (size_t)rowB0 * HID;
    const uint8_t*       pA8h = Ag8h + (size_t)rowA0 * HID;
    const uint8_t*       pA8l = Ag8l + (size_t)rowA0 * HID;
    const uint8_t*       pB8h = Bg8h + (size_t)rowB0 * HID;
    const uint8_t*       pB8l = Bg8l + (size_t)rowB0 * HID;

    float acc [4][4][4];
    float acc2[4][4][4];
#pragma unroll
    for (int mt = 0; mt < 4; mt++)
#pragma unroll
        for (int nt = 0; nt < 4; nt++)
#pragma unroll
            for (int e = 0; e < 4; e++) { acc[mt][nt][e] = 0.0f; acc2[mt][nt][e] = 0.0f; }

    auto issue = [&](int s) {
        const uint32_t st = sb + (s % NSTAGE) * STAGE_BYTES;
        const int k0 = s * 64;
#pragma unroll
        for (int i = 0; i < 16; i++) {
            int c = tid + i * 256;
            if (c < 2048) {
                int mat = c >> 10;
                int j = c & 1023, row = j >> 3, q = j & 7;
                const __nv_bfloat16* src = (mat ? pBh : pAh) + (size_t)row * HID + k0 + q * 8;
                cp_async16(st + mat * 16384 + SWZ128((uint32_t)(row * 128 + q * 16)), src);
            } else {
                int m2 = (c - 2048) >> 9;
                int j = c & 511, row = j >> 2, q = j & 3;
                const uint8_t* b8 = (m2 == 0) ? pA8h : (m2 == 1) ? pA8l
                                   : (m2 == 2) ? pB8h : pB8l;
                cp_async16(st + OFF_A8H + m2 * 8192 + SWZ64((uint32_t)(row * 64 + q * 16)),
                           b8 + (size_t)row * HID + k0 + q * 16);
            }
        }
        CP_COMMIT();
    };

    issue(0);
    issue(1);

    const int arow = wr * 64 + (lane & 15);
    const int brow = wc * 32 + (lane & 7) + ((lane >> 4) << 3);
    const int ar8  = wr * 64 + (lane & 7) + ((lane >> 3) & 1) * 8;
    const int akb  = ((lane >> 4) & 1) * 16;
    const int br8  = wc * 32 + (lane & 7) + ((lane >> 4) & 1) * 8;
    const int bkb  = ((lane >> 3) & 1) * 16;

    for (int s = 0; s < 16; s++) {
        if (s < 15) CP_WAIT(1); else CP_WAIT(0);
        __syncthreads();
        if (s + 2 < 16) issue(s + 2);

        const uint32_t st = sb + (s % NSTAGE) * STAGE_BYTES;
#pragma unroll
        for (int ks = 0; ks < 4; ks++) {
            uint32_t ah[4][4], bh[2][4];
            const int abo = ks * 32 + (lane >> 4) * 16;
            const int bbo = ks * 32 + ((lane >> 3) & 1) * 16;
#pragma unroll
            for (int mt = 0; mt < 4; mt++)
                ldsm_x4(ah[mt], st + OFF_AH + SWZ128((uint32_t)((arow + mt * 16) * 128 + abo)));
#pragma unroll
            for (int bt = 0; bt < 2; bt++)
                ldsm_x4(bh[bt], st + OFF_BH + SWZ128((uint32_t)((brow + bt * 16) * 128 + bbo)));
#pragma unroll
            for (int mt = 0; mt < 4; mt++)
#pragma unroll
                for (int nt = 0; nt < 4; nt++)
                    mma_bf16(acc[mt][nt], ah[mt], &bh[nt >> 1][(nt & 1) * 2]);
        }
#pragma unroll
        for (int kk = 0; kk < 2; kk++) {
            uint32_t a8h[4][4], a8l[4][4], b8h[2][4], b8l[2][4];
#pragma unroll
            for (int mt = 0; mt < 4; mt++) {
                uint32_t off = SWZ64((uint32_t)((ar8 + mt * 16) * 64 + kk * 32 + akb));
                ldsm_x4(a8h[mt], st + OFF_A8H + off);
                ldsm_x4(a8l[mt], st + OFF_A8L + off);
            }
#pragma unroll
            for (int bt = 0; bt < 2; bt++) {
                uint32_t off = SWZ64((uint32_t)((br8 + bt * 16) * 64 + kk * 32 + bkb));
                ldsm_x4(b8h[bt], st + OFF_B8H + off);
                ldsm_x4(b8l[bt], st + OFF_B8L + off);
            }
#pragma unroll
            for (int mt = 0; mt < 4; mt++)
#pragma unroll
                for (int nt = 0; nt < 4; nt++) {
                    mma_fp8(acc2[mt][nt], a8l[mt], &b8h[nt >> 1][(nt & 1) * 2]);
                    mma_fp8(acc2[mt][nt], a8h[mt], &b8l[nt >> 1][(nt & 1) * 2]);
                }
        }
    }
    __syncthreads();

    float* Cs = reinterpret_cast<float*>(smem);   // [128][132]
    float* at = reinterpret_cast<float*>(smem + OFF_ATTN);   // [256]
    {
        const int r0 = wr * 64 + (lane >> 2);
        const int c0 = wc * 32 + (lane & 3) * 2;
#pragma unroll
        for (int mt = 0; mt < 4; mt++)
#pragma unroll
            for (int nt = 0; nt < 4; nt++) {
                int r = r0 + mt * 16, c = c0 + nt * 8;
                float v0 = acc[mt][nt][0] + acc2[mt][nt][0] * RISCALE;
                float v1 = acc[mt][nt][1] + acc2[mt][nt][1] * RISCALE;
                float v2 = acc[mt][nt][2] + acc2[mt][nt][2] * RISCALE;
                float v3 = acc[mt][nt][3] + acc2[mt][nt][3] * RISCALE;
                *reinterpret_cast<float2*>(&Cs[r * 132 + c])       = make_float2(v0, v1);
                *reinterpret_cast<float2*>(&Cs[(r + 8) * 132 + c]) = make_float2(v2, v3);
            }
    }
    if (perm == 2) at[tid] = attn[(rowA0 >> 12) * 256 + tid];
    __syncthreads();

    if (perm == 0) {
#pragma unroll
        for (int i = 0; i < 16; i++) {
            int idx = i * 256 + tid;
            int row = idx >> 5, q = idx & 31;
            float4 v = *reinterpret_cast<const float4*>(&Cs[row * 132 + q * 4]);
            int colg = rowB0 + q * 4;
            if (bias) {
                float4 b = *reinterpret_cast<const float4*>(bias + colg);
                v.x += b.x; v.y += b.y; v.z += b.z; v.w += b.w;
            }
            *reinterpret_cast<float4*>(C + (size_t)(rowA0 + row) * HID + colg) = v;
        }
    } else if (perm == 1) {
#pragma unroll
        for (int i = 0; i < 16; i++) {
            int idx = i * 256 + tid;
            int row = idx >> 5, q = idx & 31;
            float4 v = *reinterpret_cast<const float4*>(&Cs[row * 132 + q * 4]);
            float vv[4] = {v.x, v.y, v.z, v.w};

            int m = rowA0 + row;
            int n = m >> 12;
            int s = m & 4095;
            int u = s >> 4, r = s & 15;
            int c = rowB0 + q * 4;
            int b = c >> 6, d = c & 63;
            size_t o = ((size_t)((n * 256 + u) * 16 + b)) * HID + r * 64 + d;

            float h0 = __bfloat162float(__float2bfloat16_rn(vv[0]));
            float h1 = __bfloat162float(__float2bfloat16_rn(vv[1]));
            float h2 = __bfloat162float(__float2bfloat16_rn(vv[2]));
            float h3 = __bfloat162float(__float2bfloat16_rn(vv[3]));
            uint2 hp = make_uint2(pack2bf16(vv[0], vv[1]), pack2bf16(vv[2], vv[3]));
            uint8_t h8[4] = { f2e4m3(vv[0]), f2e4m3(vv[1]), f2e4m3(vv[2]), f2e4m3(vv[3]) };
            uint8_t l8[4] = { f2e4m3((vv[0] - h0) * RSCALE), f2e4m3((vv[1] - h1) * RSCALE),
                              f2e4m3((vv[2] - h2) * RSCALE), f2e4m3((vv[3] - h3) * RSCALE) };
            *reinterpret_cast<uint2*>(Ph + o)     = hp;
            *reinterpret_cast<uint32_t*>(P8h + o) = *reinterpret_cast<uint32_t*>(h8);
            *reinterpret_cast<uint32_t*>(P8l + o) = *reinterpret_cast<uint32_t*>(l8);
        }
    } else {
        const int n  = rowA0 >> 12;
        const int u0 = (rowA0 & 4095) >> 4;
        const int g  = tid >> 5;
        const int q  = tid & 31;
        float4 bb = make_float4(0.f, 0.f, 0.f, 0.f);
        if (bias) bb = *reinterpret_cast<const float4*>(bias + rowB0 + q * 4);
#pragma unroll
        for (int a = 0; a < 16; a++) {
            float4 o4 = bb;
#pragma unroll
            for (int b = 0; b < 16; b++) {
                float w = at[a * 16 + b];
                const float* zr = &Cs[(g * 16 + b) * 132 + q * 4];
                o4.x = fmaf(w, zr[0], o4.x);
                o4.y = fmaf(w, zr[1], o4.y);
                o4.z = fmaf(w, zr[2], o4.z);
                o4.w = fmaf(w, zr[3], o4.w);
            }
            size_t orow = (size_t)n * SEQ + (size_t)a * 256 + (u0 + g);
            *reinterpret_cast<float4*>(C + orow * HID + rowB0 + q * 4) = o4;
        }
    }
}

// ============ x converts (vectorized) =======================================
__global__ __launch_bounds__(256)
void convert_x(const float* __restrict__ x)
{
    const int z  = blockIdx.z;
    const int s0 = blockIdx.y * 32;
    const int c0 = blockIdx.x * 128;
    __shared__ float tile[32][129];
    const float* xb = x + (size_t)z * SEQ * HID;

    const int r  = threadIdx.x >> 3;
    const int cc = (threadIdx.x & 7) * 16;
    float v[16];
    const float* src = xb + (size_t)(s0 + r) * HID + c0 + cc;
#pragma unroll
    for (int i = 0; i < 4; i++) {
        float4 f = *reinterpret_cast<const float4*>(src + i * 4);
        v[i * 4 + 0] = f.x; v[i * 4 + 1] = f.y;
        v[i * 4 + 2] = f.z; v[i * 4 + 3] = f.w;
    }
    __nv_bfloat16 h[16]; uint8_t h8[16], l8[16];
#pragma unroll
    for (int k = 0; k < 16; k++) {
        tile[r][cc + k] = v[k];
        h[k] = __float2bfloat16_rn(v[k]);
        float lo = v[k] - __bfloat162float(h[k]);
        h8[k] = f2e4m3(v[k]);
        l8[k] = f2e4m3(lo * RSCALE);
    }
    size_t o = ((size_t)z * SEQ + s0 + r) * HID + c0 + cc;
    *reinterpret_cast<uint4*>(g_xh + o)     = reinterpret_cast<uint4*>(h)[0];
    *reinterpret_cast<uint4*>(g_xh + o + 8) = reinterpret_cast<uint4*>(h)[1];
    *reinterpret_cast<uint4*>(g_xh8 + o)    = *reinterpret_cast<uint4*>(h8);
    *reinterpret_cast<uint4*>(g_xl8 + o)    = *reinterpret_cast<uint4*>(l8);
    __syncthreads();

    const int ch = threadIdx.x >> 1;
    const int sh = (threadIdx.x & 1) * 16;
    __nv_bfloat16 th[16], tl[16];
#pragma unroll
    for (int k = 0; k < 16; k++) {
        float vv = tile[sh + k][ch];
        __nv_bfloat16 hh = __float2bfloat16_rn(vv);
        th[k] = hh;
        tl[k] = __float2bfloat16_rn(vv - __bfloat162float(hh));
    }
    size_t ot = ((size_t)z * HID + c0 + ch) * SEQ + s0 + sh;
    *reinterpret_cast<uint4*>(g_xTh + ot)     = reinterpret_cast<uint4*>(th)[0];
    *reinterpret_cast<uint4*>(g_xTh + ot + 8) = reinterpret_cast<uint4*>(th)[1];
    *reinterpret_cast<uint4*>(g_xTl + ot)     = reinterpret_cast<uint4*>(tl)[0];
    *reinterpret_cast<uint4*>(g_xTl + ot + 8) = reinterpret_cast<uint4*>(tl)[1];
}

// ===== W converts (vectorized 32x128 transpose tiles) =======================
__global__ __launch_bounds__(256)
void convert_w(const float* __restrict__ Wk, const float* __restrict__ Wv,
               const float* __restrict__ Wo)
{
    const int z = blockIdx.z;
    const float* W = (z == 0) ? Wk : (z == 1) ? Wv : Wo;
    __shared__ float tile[32][129];
    const int k0 = blockIdx.y * 32;    // K rows of W
    const int n0 = blockIdx.x * 128;   // N cols of W

    const int r  = threadIdx.x >> 3;
    const int cc = (threadIdx.x & 7) * 16;
    const float* src = W + (size_t)(k0 + r) * HID + n0 + cc;
#pragma unroll
    for (int i = 0; i < 4; i++) {
        float4 f = *reinterpret_cast<const float4*>(src + i * 4);
        tile[r][cc + i * 4 + 0] = f.x;
        tile[r][cc + i * 4 + 1] = f.y;
        tile[r][cc + i * 4 + 2] = f.z;
        tile[r][cc + i * 4 + 3] = f.w;
    }
    __syncthreads();

    const int ch = threadIdx.x >> 1;            // 0..127: N col
    const int sh = (threadIdx.x & 1) * 16;      // K offset
    float v[16];
#pragma unroll
    for (int k = 0; k < 16; k++) v[k] = tile[sh + k][ch];

    size_t o = (size_t)(n0 + ch) * HID + k0 + sh;   // Wt[N,K]
    __nv_bfloat16 h[16];
#pragma unroll
    for (int k = 0; k < 16; k++) h[k] = __float2bfloat16_rn(v[k]);

    if (z == 0) {
        __nv_bfloat16 l[16];
#pragma unroll
        for (int k = 0; k < 16; k++)
            l[k] = __float2bfloat16_rn(v[k] - __bfloat162float(h[k]));
        *reinterpret_cast<uint4*>(g_Wkh + o)     = reinterpret_cast<uint4*>(h)[0];
        *reinterpret_cast<uint4*>(g_Wkh + o + 8) = reinterpret_cast<uint4*>(h)[1];
        *reinterpret_cast<uint4*>(g_Wkl + o)     = reinterpret_cast<uint4*>(l)[0];
        *reinterpret_cast<uint4*>(g_Wkl + o + 8) = reinterpret_cast<uint4*>(l)[1];
    } else {
        uint8_t h8[16], l8[16];
#pragma unroll
        for (int k = 0; k < 16; k++) {
            h8[k] = f2e4m3(v[k]);
            l8[k] = f2e4m3((v[k] - __bfloat162float(h[k])) * RSCALE);
        }
        if (z == 1) {
            *reinterpret_cast<uint4*>(g_Wvh + o)     = reinterpret_cast<uint4*>(h)[0];
            *reinterpret_cast<uint4*>(g_Wvh + o + 8) = reinterpret_cast<uint4*>(h)[1];
            *reinterpret_cast<uint4*>(g_Wv8h + o)    = *reinterpret_cast<uint4*>(h8);
            *reinterpret_cast<uint4*>(g_Wv8l + o)    = *reinterpret_cast<uint4*>(l8);
        } else {
            *reinterpret_cast<uint4*>(g_Woh + o)     = reinterpret_cast<uint4*>(h)[0];
            *reinterpret_cast<uint4*>(g_Woh + o + 8) = reinterpret_cast<uint4*>(h)[1];
            *reinterpret_cast<uint4*>(g_Wo8h + o)    = *reinterpret_cast<uint4*>(h8);
            *reinterpret_cast<uint4*>(g_Wo8l + o)    = *reinterpret_cast<uint4*>(l8);
        }
    }
}

// -------- Ep[n,i0b,a,b] = sum_{i in [i0,i0+16),d} Wq[i,a64+d]*T[n][i,b64+d] --
__global__ __launch_bounds__(256)
void ereduce(const float* __restrict__ Wq)
{
    const int n  = blockIdx.x;
    const int i0 = blockIdx.y * 16;
    const int tid = threadIdx.x;
    const int a = tid & 15, b = tid >> 4;

    __shared__ float qs[4][1088];
    __shared__ float ks[4][1088];

    const float* Tb = g_T + (size_t)n * HID * HID;

    float acc = 0.0f;
    for (int batch = 0; batch < 4; batch++) {
        const int irow = i0 + batch * 4;
#pragma unroll
        for (int t = 0; t < 8; t++) {
            int f  = tid + t * 256;
            int ff = f & 1023;
            int rl = ff >> 8;
            int ch = ff & 255;
            const float* src = ((f < 1024) ? Wq : Tb) + (size_t)(irow + rl) * HID + ch * 4;
            float4 v = *reinterpret_cast<const float4*>(src);
            float* dst = (f < 1024) ? qs[rl] : ks[rl];
            int c = ch * 4, d0 = c & 63, h = c >> 6;
            dst[(d0 + 0) * 17 + h] = v.x;
            dst[(d0 + 1) * 17 + h] = v.y;
            dst[(d0 + 2) * 17 + h] = v.z;
            dst[(d0 + 3) * 17 + h] = v.w;
        }
        __syncthreads();
#pragma unroll
        for (int rl = 0; rl < 4; rl++)
#pragma unroll
            for (int d = 0; d < 64; d++)
                acc = fmaf(qs[rl][d * 17 + a], ks[rl][d * 17 + b], acc);
        __syncthreads();
    }
    // non-atomic partial store: slot (n, i0-block)
    g_Ep[((size_t)n * 64 + blockIdx.y) * 256 + a * 16 + b] = acc;
}

// ---------------- softmax over b (sums 64 partials first) -------------------
__global__ void softmax_kernel()
{
    int t = threadIdx.x;
    if (t >= N_BATCH * NHEADS) return;
    int n = t >> 4, a = t & 15;

    float v[16];
#pragma unroll
    for (int b = 0; b < 16; b++) v[b] = 0.0f;
    for (int p = 0; p < 64; p++) {
        const float* e = g_Ep + ((size_t)n * 64 + p) * 256 + a * 16;
#pragma unroll
        for (int b = 0; b < 16; b += 4) {
            float4 f = *reinterpret_cast<const float4*>(e + b);
            v[b + 0] += f.x; v[b + 1] += f.y; v[b + 2] += f.z; v[b + 3] += f.w;
        }
    }

    float m = -1e30f;
#pragma unroll
    for (int b = 0; b < 16; b++) { v[b] *= 0.125f; m = fmaxf(m, v[b]); }
    float s = 0.0f;
#pragma unroll
    for (int b = 0; b < 16; b++) { v[b] = expf(v[b] - m); s += v[b]; }
    float inv = 1.0f / s;
    float* o = g_A + n * 256 + a * 16;
#pragma unroll
    for (int b = 0; b < 16; b++) o[b] = v[b] * inv;
}

// ---------------- launch ----------------------------------------------------
extern "C" void kernel_launch(void* const* d_in, const int* in_sizes, int n_in,
                              void* d_out, int out_size)
{
    const float* x  = (const float*)d_in[0];
    const float* Wq = (const float*)d_in[1];
    const float* Wk = (const float*)d_in[2];
    const float* Wv = (const float*)d_in[3];
    const float* Wo = (const float*)d_in[4];
    const float* bo = (const float*)d_in[5];
    float* out = (float*)d_out;

    float *pT, *pAtn;
    __nv_bfloat16 *pxh, *pxTh, *pxTl, *pGh, *pGl, *pAh;
    __nv_bfloat16 *pWkh, *pWkl, *pWvh, *pWoh;
    uint8_t *pxh8, *pxl8, *pA8h, *pA8l, *pWv8h, *pWv8l, *pWo8h, *pWo8l;
    cudaGetSymbolAddress((void**)&pT,  g_T);
    cudaGetSymbolAddress((void**)&pAtn, g_A);
    cudaGetSymbolAddress((void**)&pxh, g_xh);
    cudaGetSymbolAddress((void**)&pxh8, g_xh8);
    cudaGetSymbolAddress((void**)&pxl8, g_xl8);
    cudaGetSymbolAddress((void**)&pxTh, g_xTh);
    cudaGetSymbolAddress((void**)&pxTl, g_xTl);
    cudaGetSymbolAddress((void**)&pGh, g_Gh);
    cudaGetSymbolAddress((void**)&pGl, g_Gl);
    cudaGetSymbolAddress((void**)&pAh, g_Ah);
    cudaGetSymbolAddress((void**)&pA8h, g_A8h);
    cudaGetSymbolAddress((void**)&pA8l, g_A8l);
    cudaGetSymbolAddress((void**)&pWkh, g_Wkh);
    cudaGetSymbolAddress((void**)&pWkl, g_Wkl);
    cudaGetSymbolAddress((void**)&pWvh, g_Wvh);
    cudaGetSymbolAddress((void**)&pWoh, g_Woh);
    cudaGetSymbolAddress((void**)&pWv8h, g_Wv8h);
    cudaGetSymbolAddress((void**)&pWv8l, g_Wv8l);
    cudaGetSymbolAddress((void**)&pWo8h, g_Wo8h);
    cudaGetSymbolAddress((void**)&pWo8l, g_Wo8l);

    cudaFuncSetAttribute(gemm3, cudaFuncAttributeMaxDynamicSharedMemorySize, GEMM3_SMEM);
    cudaFuncSetAttribute(gemm_mixed, cudaFuncAttributeMaxDynamicSharedMemorySize, GEMM_SMEM);

    convert_x<<<dim3(HID / 128, SEQ / 32, N_BATCH), 256>>>(x);
    convert_w<<<dim3(HID / 128, HID / 32, 3), 256>>>(Wk, Wv, Wo);

    // Gram: G[n] = x[n]^T x[n]
    gemm3<<<dim3(8, 8, N_BATCH), 256, GEMM3_SMEM>>>(
        pxTh, pxTl, pxTh, pxTl, SEQ, SEQ, SEQ,
        (size_t)HID * SEQ, (size_t)HID * SEQ, (size_t)HID * HID,
        nullptr, pGh, pGl, HID, 1, 1);

    // T[n] = G[n] @ Wk
    gemm3<<<dim3(8, 8, N_BATCH), 256, GEMM3_SMEM>>>(
        pGh, pGl, pWkh, pWkl, HID, HID, HID,
        (size_t)HID * HID, 0, (size_t)HID * HID,
        pT, nullptr, nullptr, HID, 0, 0);

    ereduce<<<dim3(N_BATCH, HID / 16), 256>>>(Wq);
    softmax_kernel<<<1, 64>>>();

    // V = x @ Wv, epilogue writes permuted split operand A
    gemm_mixed<<<dim3(HID / 128, MROWS / 128), 256, GEMM_SMEM>>>(
        pxh, pxh8, pxl8, pWvh, pWv8h, pWv8l, nullptr, nullptr,
        nullptr, pAh, pA8h, pA8l, 1);

    // out = attn-mix(A @ Wo) + bo, fused epilogue
    gemm_mixed<<<dim3(HID / 128, MROWS / 128), 256, GEMM_SMEM>>>(
        pAh, pA8h, pA8l, pWoh, pWo8h, pWo8l, bo, pAtn,
        out, nullptr, nullptr, nullptr, 2);
}

// round 16
// speedup vs baseline: 1.0628x; 1.0137x over previous
#include <cuda_runtime.h>
#include <cuda_bf16.h>
#include <cuda_fp8.h>
#include <math.h>
#include <stdint.h>

#define N_BATCH 4
#define SEQ     4096
#define HID     1024
#define NHEADS  16
#define MROWS   (N_BATCH * SEQ)   // 16384

#define RSCALE 4096.0f
#define RISCALE (1.0f / 4096.0f)

// ---------------- scratch (device globals: no allocation allowed) ----------
__device__ __nv_bfloat16  g_xh  [MROWS * HID];
__device__ uint8_t        g_xh8 [MROWS * HID];
__device__ uint8_t        g_xl8 [MROWS * HID];
__device__ __nv_bfloat16  g_xTh [MROWS * HID];
__device__ __nv_bfloat16  g_xTl [MROWS * HID];
__device__ __nv_bfloat16  g_Gh  [N_BATCH * HID * HID];
__device__ __nv_bfloat16  g_Gl  [N_BATCH * HID * HID];
__device__ float          g_T   [N_BATCH * HID * HID];
__device__ __nv_bfloat16  g_Ah  [MROWS * HID];   // permuted V, bf16 hi
__device__ uint8_t        g_A8h [MROWS * HID];   // permuted V, e4m3 hi
__device__ uint8_t        g_A8l [MROWS * HID];   // permuted V, e4m3 lo*4096
__device__ __nv_bfloat16  g_Wkh [HID * HID];
__device__ __nv_bfloat16  g_Wkl [HID * HID];
__device__ __nv_bfloat16  g_Wvh [HID * HID];
__device__ uint8_t        g_Wv8h[HID * HID];
__device__ uint8_t        g_Wv8l[HID * HID];
__device__ __nv_bfloat16  g_Woh [HID * HID];
__device__ uint8_t        g_Wo8h[HID * HID];
__device__ uint8_t        g_Wo8l[HID * HID];
__device__ float          g_E [N_BATCH * NHEADS * NHEADS];
__device__ float          g_A [N_BATCH * NHEADS * NHEADS];

// ======================= PTX helpers (baseline ISA) =========================
__device__ __forceinline__ uint32_t smem_u32(const void* p) {
    uint32_t a;
    asm("{ .reg .u64 t; cvta.to.shared.u64 t, %1; cvt.u32.u64 %0, t; }" : "=r"(a) : "l"(p));
    return a;
}
#define SWZ128(o) ((o) ^ (((o) >> 3) & 0x70))
#define SWZ64(o)  ((o) ^ (((o) >> 3) & 0x30))

__device__ __forceinline__ void cp_async16(uint32_t dst, const void* src) {
    asm volatile("cp.async.cg.shared.global [%0], [%1], 16;" :: "r"(dst), "l"(src));
}
#define CP_COMMIT() asm volatile("cp.async.commit_group;" ::: "memory")
#define CP_WAIT(n)  asm volatile("cp.async.wait_group %0;" :: "n"(n) : "memory")

__device__ __forceinline__ void ldsm_x4(uint32_t* r, uint32_t addr) {
    asm volatile("ldmatrix.sync.aligned.m8n8.x4.shared.b16 {%0,%1,%2,%3}, [%4];"
        : "=r"(r[0]), "=r"(r[1]), "=r"(r[2]), "=r"(r[3]) : "r"(addr));
}
__device__ __forceinline__ void mma_bf16(float* d, const uint32_t* a, const uint32_t* b) {
    asm volatile(
        "mma.sync.aligned.m16n8k16.row.col.f32.bf16.bf16.f32 "
        "{%0,%1,%2,%3}, {%4,%5,%6,%7}, {%8,%9}, {%0,%1,%2,%3};"
        : "+f"(d[0]), "+f"(d[1]), "+f"(d[2]), "+f"(d[3])
        : "r"(a[0]), "r"(a[1]), "r"(a[2]), "r"(a[3]), "r"(b[0]), "r"(b[1]));
}
__device__ __forceinline__ void mma_fp8(float* d, const uint32_t* a, const uint32_t* b) {
    asm volatile(
        "mma.sync.aligned.m16n8k32.row.col.f32.e4m3.e4m3.f32 "
        "{%0,%1,%2,%3}, {%4,%5,%6,%7}, {%8,%9}, {%0,%1,%2,%3};"
        : "+f"(d[0]), "+f"(d[1]), "+f"(d[2]), "+f"(d[3])
        : "r"(a[0]), "r"(a[1]), "r"(a[2]), "r"(a[3]), "r"(b[0]), "r"(b[1]));
}
__device__ __forceinline__ uint8_t f2e4m3(float v) {
    __nv_fp8_e4m3 t = __nv_fp8_e4m3(v);
    return *reinterpret_cast<uint8_t*>(&t);
}
__device__ __forceinline__ uint32_t pack2bf16(float a, float b) {
    __nv_bfloat162 t = __floats2bfloat162_rn(a, b);
    return *reinterpret_cast<uint32_t*>(&t);
}

// ======================= generic bf16x3 GEMM (champion) =====================
#define STAGE3_BYTES 65536
#define GEMM3_SMEM   (3 * STAGE3_BYTES)

__global__ __launch_bounds__(256, 1)
void gemm3(const __nv_bfloat16* __restrict__ Ah_, const __nv_bfloat16* __restrict__ Al_,
           const __nv_bfloat16* __restrict__ Bh_, const __nv_bfloat16* __restrict__ Bl_,
           int lda, int ldb, int K,
           size_t sA, size_t sB, size_t sC,
           float* __restrict__ Cf_,
           __nv_bfloat16* __restrict__ Ch_, __nv_bfloat16* __restrict__ Cl_,
           int ldc, int mode, int symmetric)
{
    if (symmetric && (int)blockIdx.x < (int)blockIdx.y) return;
    extern __shared__ char smem[];
    const uint32_t sb = smem_u32(smem);
    const int tid  = threadIdx.x;
    const int wid  = tid >> 5, lane = tid & 31;
    const int wr   = wid >> 2, wc = wid & 3;
    const int z    = blockIdx.z;
    const int row0 = blockIdx.y * 128;
    const int col0 = blockIdx.x * 128;

    const __nv_bfloat16* base[4] = {
        Ah_ + (size_t)z * sA + (size_t)row0 * lda,
        Al_ + (size_t)z * sA + (size_t)row0 * lda,
        Bh_ + (size_t)z * sB + (size_t)col0 * ldb,
        Bl_ + (size_t)z * sB + (size_t)col0 * ldb };

    float acc[4][4][4];
#pragma unroll
    for (int mt = 0; mt < 4; mt++)
#pragma unroll
        for (int nt = 0; nt < 4; nt++)
#pragma unroll
            for (int e = 0; e < 4; e++) acc[mt][nt][e] = 0.0f;

    const int nst = K >> 6;

    auto issue = [&](int s) {
        const uint32_t st = sb + (s % 3) * STAGE3_BYTES;
        const int k0 = s * 64;
#pragma unroll
        for (int i = 0; i < 16; i++) {
            int c = tid + i * 256;
            int mat = c >> 10, j = c & 1023, row = j >> 3, q = j & 7;
            int ld = (mat < 2) ? lda : ldb;
            cp_async16(st + mat * 16384 + SWZ128((uint32_t)(row * 128 + q * 16)),
                       base[mat] + (size_t)row * ld + k0 + q * 8);
        }
        CP_COMMIT();
    };

    issue(0);
    issue(1);

    const int arow = wr * 64 + (lane & 15);
    const int brow = wc * 32 + (lane & 7) + ((lane >> 4) << 3);

    for (int s = 0; s < nst; s++) {
        if (s < nst - 1) CP_WAIT(1); else CP_WAIT(0);
        __syncthreads();
        if (s + 2 < nst) issue(s + 2);

        const uint32_t st = sb + (s % 3) * STAGE3_BYTES;
#pragma unroll
        for (int ks = 0; ks < 4; ks++) {
            uint32_t ah[4][4], al[4][4], bh[2][4], bl[2][4];
            const int abo = ks * 32 + (lane >> 4) * 16;
            const int bbo = ks * 32 + ((lane >> 3) & 1) * 16;
#pragma unroll
            for (int mt = 0; mt < 4; mt++) {
                uint32_t off = SWZ128((uint32_t)((arow + mt * 16) * 128 + abo));
                ldsm_x4(ah[mt], st + off);
                ldsm_x4(al[mt], st + 16384 + off);
            }
#pragma unroll
            for (int bt = 0; bt < 2; bt++) {
                uint32_t off = SWZ128((uint32_t)((brow + bt * 16) * 128 + bbo));
                ldsm_x4(bh[bt], st + 32768 + off);
                ldsm_x4(bl[bt], st + 49152 + off);
            }
#pragma unroll
            for (int mt = 0; mt < 4; mt++)
#pragma unroll
                for (int nt = 0; nt < 4; nt++) {
                    const uint32_t* bhp = &bh[nt >> 1][(nt & 1) * 2];
                    const uint32_t* blp = &bl[nt >> 1][(nt & 1) * 2];
                    mma_bf16(acc[mt][nt], ah[mt], bhp);
                    mma_bf16(acc[mt][nt], ah[mt], blp);
                    mma_bf16(acc[mt][nt], al[mt], bhp);
                }
        }
    }
    __syncthreads();

    float* Cs = reinterpret_cast<float*>(smem);   // [128][132]
    {
        const int r0 = wr * 64 + (lane >> 2);
        const int c0 = wc * 32 + (lane & 3) * 2;
#pragma unroll
        for (int mt = 0; mt < 4; mt++)
#pragma unroll
            for (int nt = 0; nt < 4; nt++) {
                int r = r0 + mt * 16, c = c0 + nt * 8;
                *reinterpret_cast<float2*>(&Cs[r * 132 + c]) =
                    make_float2(acc[mt][nt][0], acc[mt][nt][1]);
                *reinterpret_cast<float2*>(&Cs[(r + 8) * 132 + c]) =
                    make_float2(acc[mt][nt][2], acc[mt][nt][3]);
            }
    }
    __syncthreads();

    if (mode == 0) {
        float* C = Cf_ + (size_t)z * sC;
#pragma unroll
        for (int i = 0; i < 16; i++) {
            int idx = i * 256 + tid;
            int row = idx >> 5, q = idx & 31;
            float4 v = *reinterpret_cast<const float4*>(&Cs[row * 132 + q * 4]);
            *reinterpret_cast<float4*>(C + (size_t)(row0 + row) * ldc + col0 + q * 4) = v;
        }
    } else {
        __nv_bfloat16* Ch = Ch_ + (size_t)z * sC;
        __nv_bfloat16* Cl = Cl_ + (size_t)z * sC;
#pragma unroll
        for (int i = 0; i < 16; i++) {
            int idx = i * 256 + tid;
            int row = idx >> 5, q = idx & 31;
            float4 v = *reinterpret_cast<const float4*>(&Cs[row * 132 + q * 4]);
            float vv[4] = {v.x, v.y, v.z, v.w};
            float h0 = __bfloat162float(__float2bfloat16_rn(vv[0]));
            float h1 = __bfloat162float(__float2bfloat16_rn(vv[1]));
            float h2 = __bfloat162float(__float2bfloat16_rn(vv[2]));
            float h3 = __bfloat162float(__float2bfloat16_rn(vv[3]));
            uint2 hp = make_uint2(pack2bf16(vv[0], vv[1]), pack2bf16(vv[2], vv[3]));
            uint2 lp = make_uint2(pack2bf16(vv[0] - h0, vv[1] - h1),
                                  pack2bf16(vv[2] - h2, vv[3] - h3));
            size_t o = (size_t)(row0 + row) * ldc + col0 + q * 4;
            *reinterpret_cast<uint2*>(Ch + o) = hp;
            *reinterpret_cast<uint2*>(Cl + o) = lp;
        }
        if (symmetric && blockIdx.x != blockIdx.y) {
#pragma unroll
            for (int i = 0; i < 16; i++) {
                int idx = i * 256 + tid;
                int rp = idx >> 5, q = idx & 31;
                float vv[4];
#pragma unroll
                for (int e = 0; e < 4; e++) vv[e] = Cs[(q * 4 + e) * 132 + rp];
                float h0 = __bfloat162float(__float2bfloat16_rn(vv[0]));
                float h1 = __bfloat162float(__float2bfloat16_rn(vv[1]));
                float h2 = __bfloat162float(__float2bfloat16_rn(vv[2]));
                float h3 = __bfloat162float(__float2bfloat16_rn(vv[3]));
                uint2 hp = make_uint2(pack2bf16(vv[0], vv[1]), pack2bf16(vv[2], vv[3]));
                uint2 lp = make_uint2(pack2bf16(vv[0] - h0, vv[1] - h1),
                                      pack2bf16(vv[2] - h2, vv[3] - h3));
                size_t o = (size_t)(col0 + rp) * ldc + row0 + q * 4;
                *reinterpret_cast<uint2*>(Ch + o) = hp;
                *reinterpret_cast<uint2*>(Cl + o) = lp;
            }
        }
    }
}

// ======================= mixed bf16 + fp8 GEMM ==============================
// perm=0: C = A@B^T + bias (fp32 out)
// perm=1: write permuted attention operand (bf16-hi + e4m3 hi/lo)
// perm=2: fused attention mix epilogue
#define STAGE_BYTES 65536
#define NSTAGE      3
#define GEMM_SMEM   (NSTAGE * STAGE_BYTES)
#define OFF_AH   0
#define OFF_BH   16384
#define OFF_A8H  32768
#define OFF_A8L  40960
#define OFF_B8H  49152
#define OFF_B8L  57344
#define OFF_ATTN 67584     // after Cs (128*132*4 bytes)

__global__ __launch_bounds__(256, 1)
void gemm_mixed(const __nv_bfloat16* __restrict__ Agh,
                const uint8_t* __restrict__ Ag8h,
                const uint8_t* __restrict__ Ag8l,
                const __nv_bfloat16* __restrict__ Bgh,
                const uint8_t* __restrict__ Bg8h,
                const uint8_t* __restrict__ Bg8l,
                const float* __restrict__ bias,
                const float* __restrict__ attn,
                float* __restrict__ C,
                __nv_bfloat16* __restrict__ Ph,
                uint8_t* __restrict__ P8h,
                uint8_t* __restrict__ P8l,
                int perm)
{
    extern __shared__ char smem[];
    const uint32_t sb = smem_u32(smem);
    const int tid  = threadIdx.x;
    const int wid  = tid >> 5, lane = tid & 31;
    const int wr   = wid >> 2, wc = wid & 3;
    const int rowA0 = blockIdx.y * 128;
    const int rowB0 = blockIdx.x * 128;

    const __nv_bfloat16* pAh  = Agh  + (size_t)rowA0 * HID;
    const __nv_bfloat16* pBh  = Bgh  + (size_t)rowB0 * HID;
    const uint8_t*       pA8h = Ag8h + (size_t)rowA0 * HID;
    const uint8_t*       pA8l = Ag8l + (size_t)rowA0 * HID;
    const uint8_t*       pB8h = Bg8h + (size_t)rowB0 * HID;
    const uint8_t*       pB8l = Bg8l + (size_t)rowB0 * HID;

    float acc [4][4][4];
    float acc2[4][4][4];
#pragma unroll
    for (int mt = 0; mt < 4; mt++)
#pragma unroll
        for (int nt = 0; nt < 4; nt++)
#pragma unroll
            for (int e = 0; e < 4; e++) { acc[mt][nt][e] = 0.0f; acc2[mt][nt][e] = 0.0f; }

    auto issue = [&](int s) {
        const uint32_t st = sb + (s % NSTAGE) * STAGE_BYTES;
        const int k0 = s * 64;
#pragma unroll
        for (int i = 0; i < 16; i++) {
            int c = tid + i * 256;
            if (c < 2048) {
                int mat = c >> 10;
                int j = c & 1023, row = j >> 3, q = j & 7;
                const __nv_bfloat16* src = (mat ? pBh : pAh) + (size_t)row * HID + k0 + q * 8;
                cp_async16(st + mat * 16384 + SWZ128((uint32_t)(row * 128 + q * 16)), src);
            } else {
                int m2 = (c - 2048) >> 9;
                int j = c & 511, row = j >> 2, q = j & 3;
                const uint8_t* b8 = (m2 == 0) ? pA8h : (m2 == 1) ? pA8l
                                   : (m2 == 2) ? pB8h : pB8l;
                cp_async16(st + OFF_A8H + m2 * 8192 + SWZ64((uint32_t)(row * 64 + q * 16)),
                           b8 + (size_t)row * HID + k0 + q * 16);
            }
        }
        CP_COMMIT();
    };

    issue(0);
    issue(1);

    const int arow = wr * 64 + (lane & 15);
    const int brow = wc * 32 + (lane & 7) + ((lane >> 4) << 3);
    const int ar8  = wr * 64 + (lane & 7) + ((lane >> 3) & 1) * 8;
    const int akb  = ((lane >> 4) & 1) * 16;
    const int br8  = wc * 32 + (lane & 7) + ((lane >> 4) & 1) * 8;
    const int bkb  = ((lane >> 3) & 1) * 16;

    for (int s = 0; s < 16; s++) {
        if (s < 15) CP_WAIT(1); else CP_WAIT(0);
        __syncthreads();
        if (s + 2 < 16) issue(s + 2);

        const uint32_t st = sb + (s % NSTAGE) * STAGE_BYTES;
#pragma unroll
        for (int ks = 0; ks < 4; ks++) {
            uint32_t ah[4][4], bh[2][4];
            const int abo = ks * 32 + (lane >> 4) * 16;
            const int bbo = ks * 32 + ((lane >> 3) & 1) * 16;
#pragma unroll
            for (int mt = 0; mt < 4; mt++)
                ldsm_x4(ah[mt], st + OFF_AH + SWZ128((uint32_t)((arow + mt * 16) * 128 + abo)));
#pragma unroll
            for (int bt = 0; bt < 2; bt++)
                ldsm_x4(bh[bt], st + OFF_BH + SWZ128((uint32_t)((brow + bt * 16) * 128 + bbo)));
#pragma unroll
            for (int mt = 0; mt < 4; mt++)
#pragma unroll
                for (int nt = 0; nt < 4; nt++)
                    mma_bf16(acc[mt][nt], ah[mt], &bh[nt >> 1][(nt & 1) * 2]);
        }
#pragma unroll
        for (int kk = 0; kk < 2; kk++) {
            uint32_t a8h[4][4], a8l[4][4], b8h[2][4], b8l[2][4];
#pragma unroll
            for (int mt = 0; mt < 4; mt++) {
                uint32_t off = SWZ64((uint32_t)((ar8 + mt * 16) * 64 + kk * 32 + akb));
                ldsm_x4(a8h[mt], st + OFF_A8H + off);
                ldsm_x4(a8l[mt], st + OFF_A8L + off);
            }
#pragma unroll
            for (int bt = 0; bt < 2; bt++) {
                uint32_t off = SWZ64((uint32_t)((br8 + bt * 16) * 64 + kk * 32 + bkb));
                ldsm_x4(b8h[bt], st + OFF_B8H + off);
                ldsm_x4(b8l[bt], st + OFF_B8L + off);
            }
#pragma unroll
            for (int mt = 0; mt < 4; mt++)
#pragma unroll
                for (int nt = 0; nt < 4; nt++) {
                    mma_fp8(acc2[mt][nt], a8l[mt], &b8h[nt >> 1][(nt & 1) * 2]);
                    mma_fp8(acc2[mt][nt], a8h[mt], &b8l[nt >> 1][(nt & 1) * 2]);
                }
        }
    }
    __syncthreads();

    float* Cs = reinterpret_cast<float*>(smem);   // [128][132]
    float* at = reinterpret_cast<float*>(smem + OFF_ATTN);   // [256]
    {
        const int r0 = wr * 64 + (lane >> 2);
        const int c0 = wc * 32 + (lane & 3) * 2;
#pragma unroll
        for (int mt = 0; mt < 4; mt++)
#pragma unroll
            for (int nt = 0; nt < 4; nt++) {
                int r = r0 + mt * 16, c = c0 + nt * 8;
                float v0 = acc[mt][nt][0] + acc2[mt][nt][0] * RISCALE;
                float v1 = acc[mt][nt][1] + acc2[mt][nt][1] * RISCALE;
                float v2 = acc[mt][nt][2] + acc2[mt][nt][2] * RISCALE;
                float v3 = acc[mt][nt][3] + acc2[mt][nt][3] * RISCALE;
                *reinterpret_cast<float2*>(&Cs[r * 132 + c])       = make_float2(v0, v1);
                *reinterpret_cast<float2*>(&Cs[(r + 8) * 132 + c]) = make_float2(v2, v3);
            }
    }
    if (perm == 2) at[tid] = attn[(rowA0 >> 12) * 256 + tid];
    __syncthreads();

    if (perm == 0) {
#pragma unroll
        for (int i = 0; i < 16; i++) {
            int idx = i * 256 + tid;
            int row = idx >> 5, q = idx & 31;
            float4 v = *reinterpret_cast<const float4*>(&Cs[row * 132 + q * 4]);
            int colg = rowB0 + q * 4;
            if (bias) {
                float4 b = *reinterpret_cast<const float4*>(bias + colg);
                v.x += b.x; v.y += b.y; v.z += b.z; v.w += b.w;
            }
            *reinterpret_cast<float4*>(C + (size_t)(rowA0 + row) * HID + colg) = v;
        }
    } else if (perm == 1) {
#pragma unroll
        for (int i = 0; i < 16; i++) {
            int idx = i * 256 + tid;
            int row = idx >> 5, q = idx & 31;
            float4 v = *reinterpret_cast<const float4*>(&Cs[row * 132 + q * 4]);
            float vv[4] = {v.x, v.y, v.z, v.w};

            int m = rowA0 + row;
            int n = m >> 12;
            int s = m & 4095;
            int u = s >> 4, r = s & 15;
            int c = rowB0 + q * 4;
            int b = c >> 6, d = c & 63;
            size_t o = ((size_t)((n * 256 + u) * 16 + b)) * HID + r * 64 + d;

            float h0 = __bfloat162float(__float2bfloat16_rn(vv[0]));
            float h1 = __bfloat162float(__float2bfloat16_rn(vv[1]));
            float h2 = __bfloat162float(__float2bfloat16_rn(vv[2]));
            float h3 = __bfloat162float(__float2bfloat16_rn(vv[3]));
            uint2 hp = make_uint2(pack2bf16(vv[0], vv[1]), pack2bf16(vv[2], vv[3]));
            uint8_t h8[4] = { f2e4m3(vv[0]), f2e4m3(vv[1]), f2e4m3(vv[2]), f2e4m3(vv[3]) };
            uint8_t l8[4] = { f2e4m3((vv[0] - h0) * RSCALE), f2e4m3((vv[1] - h1) * RSCALE),
                              f2e4m3((vv[2] - h2) * RSCALE), f2e4m3((vv[3] - h3) * RSCALE) };
            *reinterpret_cast<uint2*>(Ph + o)     = hp;
            *reinterpret_cast<uint32_t*>(P8h + o) = *reinterpret_cast<uint32_t*>(h8);
            *reinterpret_cast<uint32_t*>(P8l + o) = *reinterpret_cast<uint32_t*>(l8);
        }
    } else {
        const int n  = rowA0 >> 12;
        const int u0 = (rowA0 & 4095) >> 4;
        const int g  = tid >> 5;
        const int q  = tid & 31;
        float4 bb = make_float4(0.f, 0.f, 0.f, 0.f);
        if (bias) bb = *reinterpret_cast<const float4*>(bias + rowB0 + q * 4);
#pragma unroll
        for (int a = 0; a < 16; a++) {
            float4 o4 = bb;
#pragma unroll
            for (int b = 0; b < 16; b++) {
                float w = at[a * 16 + b];
                const float* zr = &Cs[(g * 16 + b) * 132 + q * 4];
                o4.x = fmaf(w, zr[0], o4.x);
                o4.y = fmaf(w, zr[1], o4.y);
                o4.z = fmaf(w, zr[2], o4.z);
                o4.w = fmaf(w, zr[3], o4.w);
            }
            size_t orow = (size_t)n * SEQ + (size_t)a * 256 + (u0 + g);
            *reinterpret_cast<float4*>(C + orow * HID + rowB0 + q * 4) = o4;
        }
    }
}

// ============ x converts (vectorized) =======================================
__global__ __launch_bounds__(256)
void convert_x(const float* __restrict__ x)
{
    const int z  = blockIdx.z;
    const int s0 = blockIdx.y * 32;
    const int c0 = blockIdx.x * 128;
    __shared__ float tile[32][129];
    const float* xb = x + (size_t)z * SEQ * HID;

    const int r  = threadIdx.x >> 3;
    const int cc = (threadIdx.x & 7) * 16;
    float v[16];
    const float* src = xb + (size_t)(s0 + r) * HID + c0 + cc;
#pragma unroll
    for (int i = 0; i < 4; i++) {
        float4 f = *reinterpret_cast<const float4*>(src + i * 4);
        v[i * 4 + 0] = f.x; v[i * 4 + 1] = f.y;
        v[i * 4 + 2] = f.z; v[i * 4 + 3] = f.w;
    }
    __nv_bfloat16 h[16]; uint8_t h8[16], l8[16];
#pragma unroll
    for (int k = 0; k < 16; k++) {
        tile[r][cc + k] = v[k];
        h[k] = __float2bfloat16_rn(v[k]);
        float lo = v[k] - __bfloat162float(h[k]);
        h8[k] = f2e4m3(v[k]);
        l8[k] = f2e4m3(lo * RSCALE);
    }
    size_t o = ((size_t)z * SEQ + s0 + r) * HID + c0 + cc;
    *reinterpret_cast<uint4*>(g_xh + o)     = reinterpret_cast<uint4*>(h)[0];
    *reinterpret_cast<uint4*>(g_xh + o + 8) = reinterpret_cast<uint4*>(h)[1];
    *reinterpret_cast<uint4*>(g_xh8 + o)    = *reinterpret_cast<uint4*>(h8);
    *reinterpret_cast<uint4*>(g_xl8 + o)    = *reinterpret_cast<uint4*>(l8);
    __syncthreads();

    const int ch = threadIdx.x >> 1;
    const int sh = (threadIdx.x & 1) * 16;
    __nv_bfloat16 th[16], tl[16];
#pragma unroll
    for (int k = 0; k < 16; k++) {
        float vv = tile[sh + k][ch];
        __nv_bfloat16 hh = __float2bfloat16_rn(vv);
        th[k] = hh;
        tl[k] = __float2bfloat16_rn(vv - __bfloat162float(hh));
    }
    size_t ot = ((size_t)z * HID + c0 + ch) * SEQ + s0 + sh;
    *reinterpret_cast<uint4*>(g_xTh + ot)     = reinterpret_cast<uint4*>(th)[0];
    *reinterpret_cast<uint4*>(g_xTh + ot + 8) = reinterpret_cast<uint4*>(th)[1];
    *reinterpret_cast<uint4*>(g_xTl + ot)     = reinterpret_cast<uint4*>(tl)[0];
    *reinterpret_cast<uint4*>(g_xTl + ot + 8) = reinterpret_cast<uint4*>(tl)[1];
}

// ===== W converts (vectorized 32x128 transpose tiles) =======================
__global__ __launch_bounds__(256)
void convert_w(const float* __restrict__ Wk, const float* __restrict__ Wv,
               const float* __restrict__ Wo)
{
    const int z = blockIdx.z;
    const float* W = (z == 0) ? Wk : (z == 1) ? Wv : Wo;
    __shared__ float tile[32][129];
    const int k0 = blockIdx.y * 32;    // K rows of W
    const int n0 = blockIdx.x * 128;   // N cols of W

    const int r  = threadIdx.x >> 3;
    const int cc = (threadIdx.x & 7) * 16;
    const float* src = W + (size_t)(k0 + r) * HID + n0 + cc;
#pragma unroll
    for (int i = 0; i < 4; i++) {
        float4 f = *reinterpret_cast<const float4*>(src + i * 4);
        tile[r][cc + i * 4 + 0] = f.x;
        tile[r][cc + i * 4 + 1] = f.y;
        tile[r][cc + i * 4 + 2] = f.z;
        tile[r][cc + i * 4 + 3] = f.w;
    }
    __syncthreads();

    const int ch = threadIdx.x >> 1;            // 0..127: N col
    const int sh = (threadIdx.x & 1) * 16;      // K offset
    float v[16];
#pragma unroll
    for (int k = 0; k < 16; k++) v[k] = tile[sh + k][ch];

    size_t o = (size_t)(n0 + ch) * HID + k0 + sh;   // Wt[N,K]
    __nv_bfloat16 h[16];
#pragma unroll
    for (int k = 0; k < 16; k++) h[k] = __float2bfloat16_rn(v[k]);

    if (z == 0) {
        __nv_bfloat16 l[16];
#pragma unroll
        for (int k = 0; k < 16; k++)
            l[k] = __float2bfloat16_rn(v[k] - __bfloat162float(h[k]));
        *reinterpret_cast<uint4*>(g_Wkh + o)     = reinterpret_cast<uint4*>(h)[0];
        *reinterpret_cast<uint4*>(g_Wkh + o + 8) = reinterpret_cast<uint4*>(h)[1];
        *reinterpret_cast<uint4*>(g_Wkl + o)     = reinterpret_cast<uint4*>(l)[0];
        *reinterpret_cast<uint4*>(g_Wkl + o + 8) = reinterpret_cast<uint4*>(l)[1];
    } else {
        uint8_t h8[16], l8[16];
#pragma unroll
        for (int k = 0; k < 16; k++) {
            h8[k] = f2e4m3(v[k]);
            l8[k] = f2e4m3((v[k] - __bfloat162float(h[k])) * RSCALE);
        }
        if (z == 1) {
            *reinterpret_cast<uint4*>(g_Wvh + o)     = reinterpret_cast<uint4*>(h)[0];
            *reinterpret_cast<uint4*>(g_Wvh + o + 8) = reinterpret_cast<uint4*>(h)[1];
            *reinterpret_cast<uint4*>(g_Wv8h + o)    = *reinterpret_cast<uint4*>(h8);
            *reinterpret_cast<uint4*>(g_Wv8l + o)    = *reinterpret_cast<uint4*>(l8);
        } else {
            *reinterpret_cast<uint4*>(g_Woh + o)     = reinterpret_cast<uint4*>(h)[0];
            *reinterpret_cast<uint4*>(g_Woh + o + 8) = reinterpret_cast<uint4*>(h)[1];
            *reinterpret_cast<uint4*>(g_Wo8h + o)    = *reinterpret_cast<uint4*>(h8);
            *reinterpret_cast<uint4*>(g_Wo8l + o)    = *reinterpret_cast<uint4*>(l8);
        }
    }
}

// -------- E[n,a,b] = sum_{i,d} Wq[i, a*64+d] * T[n][i, b*64+d] --------------
__global__ __launch_bounds__(256)
void ereduce(const float* __restrict__ Wq)
{
    const int n  = blockIdx.x;
    const int i0 = blockIdx.y * 16;
    const int tid = threadIdx.x;
    const int a = tid & 15, b = tid >> 4;

    __shared__ float qs[4][1088];
    __shared__ float ks[4][1088];

    const float* Tb = g_T + (size_t)n * HID * HID;

    float acc = 0.0f;
    for (int batch = 0; batch < 4; batch++) {
        const int irow = i0 + batch * 4;
#pragma unroll
        for (int t = 0; t < 8; t++) {
            int f  = tid + t * 256;
            int ff = f & 1023;
            int rl = ff >> 8;
            int ch = ff & 255;
            const float* src = ((f < 1024) ? Wq : Tb) + (size_t)(irow + rl) * HID + ch * 4;
            float4 v = *reinterpret_cast<const float4*>(src);
            float* dst = (f < 1024) ? qs[rl] : ks[rl];
            int c = ch * 4, d0 = c & 63, h = c >> 6;
            dst[(d0 + 0) * 17 + h] = v.x;
            dst[(d0 + 1) * 17 + h] = v.y;
            dst[(d0 + 2) * 17 + h] = v.z;
            dst[(d0 + 3) * 17 + h] = v.w;
        }
        __syncthreads();
#pragma unroll
        for (int rl = 0; rl < 4; rl++)
#pragma unroll
            for (int d = 0; d < 64; d++)
                acc = fmaf(qs[rl][d * 17 + a], ks[rl][d * 17 + b], acc);
        __syncthreads();
    }
    atomicAdd(&g_E[n * 256 + a * 16 + b], acc);
}

// ---------------- softmax over b ------------------------------------------
__global__ void softmax_kernel()
{
    int t = threadIdx.x;
    if (t >= N_BATCH * NHEADS) return;
    int n = t >> 4, a = t & 15;
    const float* e = g_E + n * 256 + a * 16;
    float v[16], m = -1e30f;
#pragma unroll
    for (int b = 0; b < 16; b++) { v[b] = e[b] * 0.125f; m = fmaxf(m, v[b]); }
    float s = 0.0f;
#pragma unroll
    for (int b = 0; b < 16; b++) { v[b] = expf(v[b] - m); s += v[b]; }
    float inv = 1.0f / s;
    float* o = g_A + n * 256 + a * 16;
#pragma unroll
    for (int b = 0; b < 16; b++) o[b] = v[b] * inv;
}

// ---------------- launch ----------------------------------------------------
extern "C" void kernel_launch(void* const* d_in, const int* in_sizes, int n_in,
                              void* d_out, int out_size)
{
    const float* x  = (const float*)d_in[0];
    const float* Wq = (const float*)d_in[1];
    const float* Wk = (const float*)d_in[2];
    const float* Wv = (const float*)d_in[3];
    const float* Wo = (const float*)d_in[4];
    const float* bo = (const float*)d_in[5];
    float* out = (float*)d_out;

    float *pT, *pE, *pAtn;
    __nv_bfloat16 *pxh, *pxTh, *pxTl, *pGh, *pGl, *pAh;
    __nv_bfloat16 *pWkh, *pWkl, *pWvh, *pWoh;
    uint8_t *pxh8, *pxl8, *pA8h, *pA8l, *pWv8h, *pWv8l, *pWo8h, *pWo8l;
    cudaGetSymbolAddress((void**)&pT,  g_T);
    cudaGetSymbolAddress((void**)&pE,  g_E);
    cudaGetSymbolAddress((void**)&pAtn, g_A);
    cudaGetSymbolAddress((void**)&pxh, g_xh);
    cudaGetSymbolAddress((void**)&pxh8, g_xh8);
    cudaGetSymbolAddress((void**)&pxl8, g_xl8);
    cudaGetSymbolAddress((void**)&pxTh, g_xTh);
    cudaGetSymbolAddress((void**)&pxTl, g_xTl);
    cudaGetSymbolAddress((void**)&pGh, g_Gh);
    cudaGetSymbolAddress((void**)&pGl, g_Gl);
    cudaGetSymbolAddress((void**)&pAh, g_Ah);
    cudaGetSymbolAddress((void**)&pA8h, g_A8h);
    cudaGetSymbolAddress((void**)&pA8l, g_A8l);
    cudaGetSymbolAddress((void**)&pWkh, g_Wkh);
    cudaGetSymbolAddress((void**)&pWkl, g_Wkl);
    cudaGetSymbolAddress((void**)&pWvh, g_Wvh);
    cudaGetSymbolAddress((void**)&pWoh, g_Woh);
    cudaGetSymbolAddress((void**)&pWv8h, g_Wv8h);
    cudaGetSymbolAddress((void**)&pWv8l, g_Wv8l);
    cudaGetSymbolAddress((void**)&pWo8h, g_Wo8h);
    cudaGetSymbolAddress((void**)&pWo8l, g_Wo8l);

    cudaFuncSetAttribute(gemm3, cudaFuncAttributeMaxDynamicSharedMemorySize, GEMM3_SMEM);
    cudaFuncSetAttribute(gemm_mixed, cudaFuncAttributeMaxDynamicSharedMemorySize, GEMM_SMEM);

    convert_x<<<dim3(HID / 128, SEQ / 32, N_BATCH), 256>>>(x);
    convert_w<<<dim3(HID / 128, HID / 32, 3), 256>>>(Wk, Wv, Wo);

    // Gram: G[n] = x[n]^T x[n]
    gemm3<<<dim3(8, 8, N_BATCH), 256, GEMM3_SMEM>>>(
        pxTh, pxTl, pxTh, pxTl, SEQ, SEQ, SEQ,
        (size_t)HID * SEQ, (size_t)HID * SEQ, (size_t)HID * HID,
        nullptr, pGh, pGl, HID, 1, 1);

    // T[n] = G[n] @ Wk
    gemm3<<<dim3(8, 8, N_BATCH), 256, GEMM3_SMEM>>>(
        pGh, pGl, pWkh, pWkl, HID, HID, HID,
        (size_t)HID * HID, 0, (size_t)HID * HID,
        pT, nullptr, nullptr, HID, 0, 0);

    cudaMemsetAsync(pE, 0, N_BATCH * NHEADS * NHEADS * sizeof(float), 0);
    ereduce<<<dim3(N_BATCH, HID / 16), 256>>>(Wq);
    softmax_kernel<<<1, 64>>>();

    // V = x @ Wv, epilogue writes permuted split operand A
    gemm_mixed<<<dim3(HID / 128, MROWS / 128), 256, GEMM_SMEM>>>(
        pxh, pxh8, pxl8, pWvh, pWv8h, pWv8l, nullptr, nullptr,
        nullptr, pAh, pA8h, pA8l, 1);

    // out = attn-mix(A @ Wo) + bo, fused epilogue
    gemm_mixed<<<dim3(HID / 128, MROWS / 128), 256, GEMM_SMEM>>>(
        pAh, pA8h, pA8l, pWoh, pWo8h, pWo8l, bo, pAtn,
        out, nullptr, nullptr, nullptr, 2);
}

// round 17
// speedup vs baseline: 1.0977x; 1.0329x over previous
#include <cuda_runtime.h>
#include <cuda_bf16.h>
#include <cuda_fp16.h>
#include <cuda_fp8.h>
#include <math.h>
#include <stdint.h>

#define N_BATCH 4
#define SEQ     4096
#define HID     1024
#define NHEADS  16
#define MROWS   (N_BATCH * SEQ)   // 16384

#define RSCALE 4096.0f
#define RISCALE (1.0f / 4096.0f)

// ---------------- scratch (device globals: no allocation allowed) ----------
__device__ __nv_bfloat16  g_xh  [MROWS * HID];
__device__ uint8_t        g_xh8 [MROWS * HID];
__device__ uint8_t        g_xl8 [MROWS * HID];
__device__ __nv_bfloat16  g_xTh [MROWS * HID];
__device__ __nv_bfloat16  g_xTl [MROWS * HID];
__device__ __nv_bfloat16  g_Gh  [N_BATCH * HID * HID];
__device__ __nv_bfloat16  g_Gl  [N_BATCH * HID * HID];
__device__ float          g_T   [N_BATCH * HID * HID];
__device__ __nv_bfloat16  g_Ah  [MROWS * HID];   // permuted V, bf16 hi
__device__ uint8_t        g_A8h [MROWS * HID];   // permuted V, e4m3 hi
__device__ uint8_t        g_A8l [MROWS * HID];   // permuted V, e4m3 lo*4096
__device__ __nv_bfloat16  g_Wkh [HID * HID];
__device__ __nv_bfloat16  g_Wkl [HID * HID];
__device__ __nv_bfloat16  g_Wvh [HID * HID];
__device__ uint8_t        g_Wv8h[HID * HID];
__device__ uint8_t        g_Wv8l[HID * HID];
__device__ __nv_bfloat16  g_Woh [HID * HID];
__device__ uint8_t        g_Wo8h[HID * HID];
__device__ uint8_t        g_Wo8l[HID * HID];
__device__ float          g_E [N_BATCH * NHEADS * NHEADS];
__device__ float          g_A [N_BATCH * NHEADS * NHEADS];

// ======================= PTX helpers (baseline ISA) =========================
__device__ __forceinline__ uint32_t smem_u32(const void* p) {
    uint32_t a;
    asm("{ .reg .u64 t; cvta.to.shared.u64 t, %1; cvt.u32.u64 %0, t; }" : "=r"(a) : "l"(p));
    return a;
}
#define SWZ128(o) ((o) ^ (((o) >> 3) & 0x70))
#define SWZ64(o)  ((o) ^ (((o) >> 3) & 0x30))

__device__ __forceinline__ void cp_async16(uint32_t dst, const void* src) {
    asm volatile("cp.async.cg.shared.global [%0], [%1], 16;" :: "r"(dst), "l"(src));
}
#define CP_COMMIT() asm volatile("cp.async.commit_group;" ::: "memory")
#define CP_WAIT(n)  asm volatile("cp.async.wait_group %0;" :: "n"(n) : "memory")

__device__ __forceinline__ void ldsm_x4(uint32_t* r, uint32_t addr) {
    asm volatile("ldmatrix.sync.aligned.m8n8.x4.shared.b16 {%0,%1,%2,%3}, [%4];"
        : "=r"(r[0]), "=r"(r[1]), "=r"(r[2]), "=r"(r[3]) : "r"(addr));
}
__device__ __forceinline__ void mma_bf16(float* d, const uint32_t* a, const uint32_t* b) {
    asm volatile(
        "mma.sync.aligned.m16n8k16.row.col.f32.bf16.bf16.f32 "
        "{%0,%1,%2,%3}, {%4,%5,%6,%7}, {%8,%9}, {%0,%1,%2,%3};"
        : "+f"(d[0]), "+f"(d[1]), "+f"(d[2]), "+f"(d[3])
        : "r"(a[0]), "r"(a[1]), "r"(a[2]), "r"(a[3]), "r"(b[0]), "r"(b[1]));
}
// fp8 mma with f16 accumulation (rate probe: possibly 2x f32-accum rate)
__device__ __forceinline__ void mma_fp8_h(uint32_t* d, const uint32_t* a, const uint32_t* b) {
    asm volatile(
        "mma.sync.aligned.m16n8k32.row.col.f16.e4m3.e4m3.f16 "
        "{%0,%1}, {%2,%3,%4,%5}, {%6,%7}, {%0,%1};"
        : "+r"(d[0]), "+r"(d[1])
        : "r"(a[0]), "r"(a[1]), "r"(a[2]), "r"(a[3]), "r"(b[0]), "r"(b[1]));
}
__device__ __forceinline__ uint8_t f2e4m3(float v) {
    __nv_fp8_e4m3 t = __nv_fp8_e4m3(v);
    return *reinterpret_cast<uint8_t*>(&t);
}
__device__ __forceinline__ uint32_t pack2bf16(float a, float b) {
    __nv_bfloat162 t = __floats2bfloat162_rn(a, b);
    return *reinterpret_cast<uint32_t*>(&t);
}

// ======================= generic bf16x3 GEMM (champion) =====================
#define STAGE3_BYTES 65536
#define GEMM3_SMEM   (3 * STAGE3_BYTES)

__global__ __launch_bounds__(256, 1)
void gemm3(const __nv_bfloat16* __restrict__ Ah_, const __nv_bfloat16* __restrict__ Al_,
           const __nv_bfloat16* __restrict__ Bh_, const __nv_bfloat16* __restrict__ Bl_,
           int lda, int ldb, int K,
           size_t sA, size_t sB, size_t sC,
           float* __restrict__ Cf_,
           __nv_bfloat16* __restrict__ Ch_, __nv_bfloat16* __restrict__ Cl_,
           int ldc, int mode, int symmetric)
{
    if (symmetric && (int)blockIdx.x < (int)blockIdx.y) return;
    extern __shared__ char smem[];
    const uint32_t sb = smem_u32(smem);
    const int tid  = threadIdx.x;
    const int wid  = tid >> 5, lane = tid & 31;
    const int wr   = wid >> 2, wc = wid & 3;
    const int z    = blockIdx.z;
    const int row0 = blockIdx.y * 128;
    const int col0 = blockIdx.x * 128;

    const __nv_bfloat16* base[4] = {
        Ah_ + (size_t)z * sA + (size_t)row0 * lda,
        Al_ + (size_t)z * sA + (size_t)row0 * lda,
        Bh_ + (size_t)z * sB + (size_t)col0 * ldb,
        Bl_ + (size_t)z * sB + (size_t)col0 * ldb };

    float acc[4][4][4];
#pragma unroll
    for (int mt = 0; mt < 4; mt++)
#pragma unroll
        for (int nt = 0; nt < 4; nt++)
#pragma unroll
            for (int e = 0; e < 4; e++) acc[mt][nt][e] = 0.0f;

    const int nst = K >> 6;

    auto issue = [&](int s) {
        const uint32_t st = sb + (s % 3) * STAGE3_BYTES;
        const int k0 = s * 64;
#pragma unroll
        for (int i = 0; i < 16; i++) {
            int c = tid + i * 256;
            int mat = c >> 10, j = c & 1023, row = j >> 3, q = j & 7;
            int ld = (mat < 2) ? lda : ldb;
            cp_async16(st + mat * 16384 + SWZ128((uint32_t)(row * 128 + q * 16)),
                       base[mat] + (size_t)row * ld + k0 + q * 8);
        }
        CP_COMMIT();
    };

    issue(0);
    issue(1);

    const int arow = wr * 64 + (lane & 15);
    const int brow = wc * 32 + (lane & 7) + ((lane >> 4) << 3);

    for (int s = 0; s < nst; s++) {
        if (s < nst - 1) CP_WAIT(1); else CP_WAIT(0);
        __syncthreads();
        if (s + 2 < nst) issue(s + 2);

        const uint32_t st = sb + (s % 3) * STAGE3_BYTES;
#pragma unroll
        for (int ks = 0; ks < 4; ks++) {
            uint32_t ah[4][4], al[4][4], bh[2][4], bl[2][4];
            const int abo = ks * 32 + (lane >> 4) * 16;
            const int bbo = ks * 32 + ((lane >> 3) & 1) * 16;
#pragma unroll
            for (int mt = 0; mt < 4; mt++) {
                uint32_t off = SWZ128((uint32_t)((arow + mt * 16) * 128 + abo));
                ldsm_x4(ah[mt], st + off);
                ldsm_x4(al[mt], st + 16384 + off);
            }
#pragma unroll
            for (int bt = 0; bt < 2; bt++) {
                uint32_t off = SWZ128((uint32_t)((brow + bt * 16) * 128 + bbo));
                ldsm_x4(bh[bt], st + 32768 + off);
                ldsm_x4(bl[bt], st + 49152 + off);
            }
#pragma unroll
            for (int mt = 0; mt < 4; mt++)
#pragma unroll
                for (int nt = 0; nt < 4; nt++) {
                    const uint32_t* bhp = &bh[nt >> 1][(nt & 1) * 2];
                    const uint32_t* blp = &bl[nt >> 1][(nt & 1) * 2];
                    mma_bf16(acc[mt][nt], ah[mt], bhp);
                    mma_bf16(acc[mt][nt], ah[mt], blp);
                    mma_bf16(acc[mt][nt], al[mt], bhp);
                }
        }
    }
    __syncthreads();

    float* Cs = reinterpret_cast<float*>(smem);   // [128][132]
    {
        const int r0 = wr * 64 + (lane >> 2);
        const int c0 = wc * 32 + (lane & 3) * 2;
#pragma unroll
        for (int mt = 0; mt < 4; mt++)
#pragma unroll
            for (int nt = 0; nt < 4; nt++) {
                int r = r0 + mt * 16, c = c0 + nt * 8;
                *reinterpret_cast<float2*>(&Cs[r * 132 + c]) =
                    make_float2(acc[mt][nt][0], acc[mt][nt][1]);
                *reinterpret_cast<float2*>(&Cs[(r + 8) * 132 + c]) =
                    make_float2(acc[mt][nt][2], acc[mt][nt][3]);
            }
    }
    __syncthreads();

    if (mode == 0) {
        float* C = Cf_ + (size_t)z * sC;
#pragma unroll
        for (int i = 0; i < 16; i++) {
            int idx = i * 256 + tid;
            int row = idx >> 5, q = idx & 31;
            float4 v = *reinterpret_cast<const float4*>(&Cs[row * 132 + q * 4]);
            *reinterpret_cast<float4*>(C + (size_t)(row0 + row) * ldc + col0 + q * 4) = v;
        }
    } else {
        __nv_bfloat16* Ch = Ch_ + (size_t)z * sC;
        __nv_bfloat16* Cl = Cl_ + (size_t)z * sC;
#pragma unroll
        for (int i = 0; i < 16; i++) {
            int idx = i * 256 + tid;
            int row = idx >> 5, q = idx & 31;
            float4 v = *reinterpret_cast<const float4*>(&Cs[row * 132 + q * 4]);
            float vv[4] = {v.x, v.y, v.z, v.w};
            float h0 = __bfloat162float(__float2bfloat16_rn(vv[0]));
            float h1 = __bfloat162float(__float2bfloat16_rn(vv[1]));
            float h2 = __bfloat162float(__float2bfloat16_rn(vv[2]));
            float h3 = __bfloat162float(__float2bfloat16_rn(vv[3]));
            uint2 hp = make_uint2(pack2bf16(vv[0], vv[1]), pack2bf16(vv[2], vv[3]));
            uint2 lp = make_uint2(pack2bf16(vv[0] - h0, vv[1] - h1),
                                  pack2bf16(vv[2] - h2, vv[3] - h3));
            size_t o = (size_t)(row0 + row) * ldc + col0 + q * 4;
            *reinterpret_cast<uint2*>(Ch + o) = hp;
            *reinterpret_cast<uint2*>(Cl + o) = lp;
        }
        if (symmetric && blockIdx.x != blockIdx.y) {
#pragma unroll
            for (int i = 0; i < 16; i++) {
                int idx = i * 256 + tid;
                int rp = idx >> 5, q = idx & 31;
                float vv[4];
#pragma unroll
                for (int e = 0; e < 4; e++) vv[e] = Cs[(q * 4 + e) * 132 + rp];
                float h0 = __bfloat162float(__float2bfloat16_rn(vv[0]));
                float h1 = __bfloat162float(__float2bfloat16_rn(vv[1]));
                float h2 = __bfloat162float(__float2bfloat16_rn(vv[2]));
                float h3 = __bfloat162float(__float2bfloat16_rn(vv[3]));
                uint2 hp = make_uint2(pack2bf16(vv[0], vv[1]), pack2bf16(vv[2], vv[3]));
                uint2 lp = make_uint2(pack2bf16(vv[0] - h0, vv[1] - h1),
                                      pack2bf16(vv[2] - h2, vv[3] - h3));
                size_t o = (size_t)(col0 + rp) * ldc + row0 + q * 4;
                *reinterpret_cast<uint2*>(Ch + o) = hp;
                *reinterpret_cast<uint2*>(Cl + o) = lp;
            }
        }
    }
}

// ======================= mixed bf16 + fp8(f16-acc) GEMM =====================
// perm=0: C = A@B^T + bias (fp32 out)
// perm=1: write permuted attention operand (bf16-hi + e4m3 hi/lo)
// perm=2: fused attention mix epilogue
#define STAGE_BYTES 65536
#define NSTAGE      3
#define GEMM_SMEM   (NSTAGE * STAGE_BYTES)
#define OFF_AH   0
#define OFF_BH   16384
#define OFF_A8H  32768
#define OFF_A8L  40960
#define OFF_B8H  49152
#define OFF_B8L  57344
#define OFF_ATTN 67584     // after Cs (128*132*4 bytes)

__global__ __launch_bounds__(256, 1)
void gemm_mixed(const __nv_bfloat16* __restrict__ Agh,
                const uint8_t* __restrict__ Ag8h,
                const uint8_t* __restrict__ Ag8l,
                const __nv_bfloat16* __restrict__ Bgh,
                const uint8_t* __restrict__ Bg8h,
                const uint8_t* __restrict__ Bg8l,
                const float* __restrict__ bias,
                const float* __restrict__ attn,
                float* __restrict__ C,
                __nv_bfloat16* __restrict__ Ph,
                uint8_t* __restrict__ P8h,
                uint8_t* __restrict__ P8l,
                int perm)
{
    extern __shared__ char smem[];
    const uint32_t sb = smem_u32(smem);
    const int tid  = threadIdx.x;
    const int wid  = tid >> 5, lane = tid & 31;
    const int wr   = wid >> 2, wc = wid & 3;
    const int rowA0 = blockIdx.y * 128;
    const int rowB0 = blockIdx.x * 128;

    const __nv_bfloat16* pAh  = Agh  + (size_t)rowA0 * HID;
    const __nv_bfloat16* pBh  = Bgh  + (size_t)rowB0 * HID;
    const uint8_t*       pA8h = Ag8h + (size_t)rowA0 * HID;
    const uint8_t*       pA8l = Ag8l + (size_t)rowA0 * HID;
    const uint8_t*       pB8h = Bg8h + (size_t)rowB0 * HID;
    const uint8_t*       pB8l = Bg8l + (size_t)rowB0 * HID;

    float    acc [4][4][4];
    uint32_t acc2[4][4][2];   // f16x2 accumulators for fp8 corrections
#pragma unroll
    for (int mt = 0; mt < 4; mt++)
#pragma unroll
        for (int nt = 0; nt < 4; nt++) {
#pragma unroll
            for (int e = 0; e < 4; e++) acc[mt][nt][e] = 0.0f;
            acc2[mt][nt][0] = 0u; acc2[mt][nt][1] = 0u;
        }

    auto issue = [&](int s) {
        const uint32_t st = sb + (s % NSTAGE) * STAGE_BYTES;
        const int k0 = s * 64;
#pragma unroll
        for (int i = 0; i < 16; i++) {
            int c = tid + i * 256;
            if (c < 2048) {
                int mat = c >> 10;
                int j = c & 1023, row = j >> 3, q = j & 7;
                const __nv_bfloat16* src = (mat ? pBh : pAh) + (size_t)row * HID + k0 + q * 8;
                cp_async16(st + mat * 16384 + SWZ128((uint32_t)(row * 128 + q * 16)), src);
            } else {
                int m2 = (c - 2048) >> 9;
                int j = c & 511, row = j >> 2, q = j & 3;
                const uint8_t* b8 = (m2 == 0) ? pA8h : (m2 == 1) ? pA8l
                                   : (m2 == 2) ? pB8h : pB8l;
                cp_async16(st + OFF_A8H + m2 * 8192 + SWZ64((uint32_t)(row * 64 + q * 16)),
                           b8 + (size_t)row * HID + k0 + q * 16);
            }
        }
        CP_COMMIT();
    };

    issue(0);
    issue(1);

    const int arow = wr * 64 + (lane & 15);
    const int brow = wc * 32 + (lane & 7) + ((lane >> 4) << 3);
    const int ar8  = wr * 64 + (lane & 7) + ((lane >> 3) & 1) * 8;
    const int akb  = ((lane >> 4) & 1) * 16;
    const int br8  = wc * 32 + (lane & 7) + ((lane >> 4) & 1) * 8;
    const int bkb  = ((lane >> 3) & 1) * 16;

    for (int s = 0; s < 16; s++) {
        if (s < 15) CP_WAIT(1); else CP_WAIT(0);
        __syncthreads();
        if (s + 2 < 16) issue(s + 2);

        const uint32_t st = sb + (s % NSTAGE) * STAGE_BYTES;
#pragma unroll
        for (int ks = 0; ks < 4; ks++) {
            uint32_t ah[4][4], bh[2][4];
            const int abo = ks * 32 + (lane >> 4) * 16;
            const int bbo = ks * 32 + ((lane >> 3) & 1) * 16;
#pragma unroll
            for (int mt = 0; mt < 4; mt++)
                ldsm_x4(ah[mt], st + OFF_AH + SWZ128((uint32_t)((arow + mt * 16) * 128 + abo)));
#pragma unroll
            for (int bt = 0; bt < 2; bt++)
                ldsm_x4(bh[bt], st + OFF_BH + SWZ128((uint32_t)((brow + bt * 16) * 128 + bbo)));
#pragma unroll
            for (int mt = 0; mt < 4; mt++)
#pragma unroll
                for (int nt = 0; nt < 4; nt++)
                    mma_bf16(acc[mt][nt], ah[mt], &bh[nt >> 1][(nt & 1) * 2]);
        }
#pragma unroll
        for (int kk = 0; kk < 2; kk++) {
            uint32_t a8h[4][4], a8l[4][4], b8h[2][4], b8l[2][4];
#pragma unroll
            for (int mt = 0; mt < 4; mt++) {
                uint32_t off = SWZ64((uint32_t)((ar8 + mt * 16) * 64 + kk * 32 + akb));
                ldsm_x4(a8h[mt], st + OFF_A8H + off);
                ldsm_x4(a8l[mt], st + OFF_A8L + off);
            }
#pragma unroll
            for (int bt = 0; bt < 2; bt++) {
                uint32_t off = SWZ64((uint32_t)((br8 + bt * 16) * 64 + kk * 32 + bkb));
                ldsm_x4(b8h[bt], st + OFF_B8H + off);
                ldsm_x4(b8l[bt], st + OFF_B8L + off);
            }
#pragma unroll
            for (int mt = 0; mt < 4; mt++)
#pragma unroll
                for (int nt = 0; nt < 4; nt++) {
                    mma_fp8_h(acc2[mt][nt], a8l[mt], &b8h[nt >> 1][(nt & 1) * 2]);
                    mma_fp8_h(acc2[mt][nt], a8h[mt], &b8l[nt >> 1][(nt & 1) * 2]);
                }
        }
    }
    __syncthreads();

    float* Cs = reinterpret_cast<float*>(smem);   // [128][132]
    float* at = reinterpret_cast<float*>(smem + OFF_ATTN);   // [256]
    {
        const int r0 = wr * 64 + (lane >> 2);
        const int c0 = wc * 32 + (lane & 3) * 2;
#pragma unroll
        for (int mt = 0; mt < 4; mt++)
#pragma unroll
            for (int nt = 0; nt < 4; nt++) {
                int r = r0 + mt * 16, c = c0 + nt * 8;
                __half2 c01 = *reinterpret_cast<__half2*>(&acc2[mt][nt][0]);
                __half2 c23 = *reinterpret_cast<__half2*>(&acc2[mt][nt][1]);
                float v0 = acc[mt][nt][0] + __half2float(__low2half(c01))  * RISCALE;
                float v1 = acc[mt][nt][1] + __half2float(__high2half(c01)) * RISCALE;
                float v2 = acc[mt][nt][2] + __half2float(__low2half(c23))  * RISCALE;
                float v3 = acc[mt][nt][3] + __half2float(__high2half(c23)) * RISCALE;
                *reinterpret_cast<float2*>(&Cs[r * 132 + c])       = make_float2(v0, v1);
                *reinterpret_cast<float2*>(&Cs[(r + 8) * 132 + c]) = make_float2(v2, v3);
            }
    }
    if (perm == 2) at[tid] = attn[(rowA0 >> 12) * 256 + tid];
    __syncthreads();

    if (perm == 0) {
#pragma unroll
        for (int i = 0; i < 16; i++) {
            int idx = i * 256 + tid;
            int row = idx >> 5, q = idx & 31;
            float4 v = *reinterpret_cast<const float4*>(&Cs[row * 132 + q * 4]);
            int colg = rowB0 + q * 4;
            if (bias) {
                float4 b = *reinterpret_cast<const float4*>(bias + colg);
                v.x += b.x; v.y += b.y; v.z += b.z; v.w += b.w;
            }
            *reinterpret_cast<float4*>(C + (size_t)(rowA0 + row) * HID + colg) = v;
        }
    } else if (perm == 1) {
#pragma unroll
        for (int i = 0; i < 16; i++) {
            int idx = i * 256 + tid;
            int row = idx >> 5, q = idx & 31;
            float4 v = *reinterpret_cast<const float4*>(&Cs[row * 132 + q * 4]);
            float vv[4] = {v.x, v.y, v.z, v.w};

            int m = rowA0 + row;
            int n = m >> 12;
            int s = m & 4095;
            int u = s >> 4, r = s & 15;
            int c = rowB0 + q * 4;
            int b = c >> 6, d = c & 63;
            size_t o = ((size_t)((n * 256 + u) * 16 + b)) * HID + r * 64 + d;

            float h0 = __bfloat162float(__float2bfloat16_rn(vv[0]));
            float h1 = __bfloat162float(__float2bfloat16_rn(vv[1]));
            float h2 = __bfloat162float(__float2bfloat16_rn(vv[2]));
            float h3 = __bfloat162float(__float2bfloat16_rn(vv[3]));
            uint2 hp = make_uint2(pack2bf16(vv[0], vv[1]), pack2bf16(vv[2], vv[3]));
            uint8_t h8[4] = { f2e4m3(vv[0]), f2e4m3(vv[1]), f2e4m3(vv[2]), f2e4m3(vv[3]) };
            uint8_t l8[4] = { f2e4m3((vv[0] - h0) * RSCALE), f2e4m3((vv[1] - h1) * RSCALE),
                              f2e4m3((vv[2] - h2) * RSCALE), f2e4m3((vv[3] - h3) * RSCALE) };
            *reinterpret_cast<uint2*>(Ph + o)     = hp;
            *reinterpret_cast<uint32_t*>(P8h + o) = *reinterpret_cast<uint32_t*>(h8);
            *reinterpret_cast<uint32_t*>(P8l + o) = *reinterpret_cast<uint32_t*>(l8);
        }
    } else {
        const int n  = rowA0 >> 12;
        const int u0 = (rowA0 & 4095) >> 4;
        const int g  = tid >> 5;
        const int q  = tid & 31;
        float4 bb = make_float4(0.f, 0.f, 0.f, 0.f);
        if (bias) bb = *reinterpret_cast<const float4*>(bias + rowB0 + q * 4);
#pragma unroll
        for (int a = 0; a < 16; a++) {
            float4 o4 = bb;
#pragma unroll
            for (int b = 0; b < 16; b++) {
                float w = at[a * 16 + b];
                const float* zr = &Cs[(g * 16 + b) * 132 + q * 4];
                o4.x = fmaf(w, zr[0], o4.x);
                o4.y = fmaf(w, zr[1], o4.y);
                o4.z = fmaf(w, zr[2], o4.z);
                o4.w = fmaf(w, zr[3], o4.w);
            }
            size_t orow = (size_t)n * SEQ + (size_t)a * 256 + (u0 + g);
            *reinterpret_cast<float4*>(C + orow * HID + rowB0 + q * 4) = o4;
        }
    }
}

// ============ x converts (vectorized) =======================================
__global__ __launch_bounds__(256)
void convert_x(const float* __restrict__ x)
{
    const int z  = blockIdx.z;
    const int s0 = blockIdx.y * 32;
    const int c0 = blockIdx.x * 128;
    __shared__ float tile[32][129];
    const float* xb = x + (size_t)z * SEQ * HID;

    const int r  = threadIdx.x >> 3;
    const int cc = (threadIdx.x & 7) * 16;
    float v[16];
    const float* src = xb + (size_t)(s0 + r) * HID + c0 + cc;
#pragma unroll
    for (int i = 0; i < 4; i++) {
        float4 f = *reinterpret_cast<const float4*>(src + i * 4);
        v[i * 4 + 0] = f.x; v[i * 4 + 1] = f.y;
        v[i * 4 + 2] = f.z; v[i * 4 + 3] = f.w;
    }
    __nv_bfloat16 h[16]; uint8_t h8[16], l8[16];
#pragma unroll
    for (int k = 0; k < 16; k++) {
        tile[r][cc + k] = v[k];
        h[k] = __float2bfloat16_rn(v[k]);
        float lo = v[k] - __bfloat162float(h[k]);
        h8[k] = f2e4m3(v[k]);
        l8[k] = f2e4m3(lo * RSCALE);
    }
    size_t o = ((size_t)z * SEQ + s0 + r) * HID + c0 + cc;
    *reinterpret_cast<uint4*>(g_xh + o)     = reinterpret_cast<uint4*>(h)[0];
    *reinterpret_cast<uint4*>(g_xh + o + 8) = reinterpret_cast<uint4*>(h)[1];
    *reinterpret_cast<uint4*>(g_xh8 + o)    = *reinterpret_cast<uint4*>(h8);
    *reinterpret_cast<uint4*>(g_xl8 + o)    = *reinterpret_cast<uint4*>(l8);
    __syncthreads();

    const int ch = threadIdx.x >> 1;
    const int sh = (threadIdx.x & 1) * 16;
    __nv_bfloat16 th[16], tl[16];
#pragma unroll
    for (int k = 0; k < 16; k++) {
        float vv = tile[sh + k][ch];
        __nv_bfloat16 hh = __float2bfloat16_rn(vv);
        th[k] = hh;
        tl[k] = __float2bfloat16_rn(vv - __bfloat162float(hh));
    }
    size_t ot = ((size_t)z * HID + c0 + ch) * SEQ + s0 + sh;
    *reinterpret_cast<uint4*>(g_xTh + ot)     = reinterpret_cast<uint4*>(th)[0];
    *reinterpret_cast<uint4*>(g_xTh + ot + 8) = reinterpret_cast<uint4*>(th)[1];
    *reinterpret_cast<uint4*>(g_xTl + ot)     = reinterpret_cast<uint4*>(tl)[0];
    *reinterpret_cast<uint4*>(g_xTl + ot + 8) = reinterpret_cast<uint4*>(tl)[1];
}

// ===== W converts (vectorized 32x128 transpose tiles) =======================
__global__ __launch_bounds__(256)
void convert_w(const float* __restrict__ Wk, const float* __restrict__ Wv,
               const float* __restrict__ Wo)
{
    const int z = blockIdx.z;
    const float* W = (z == 0) ? Wk : (z == 1) ? Wv : Wo;
    __shared__ float tile[32][129];
    const int k0 = blockIdx.y * 32;
    const int n0 = blockIdx.x * 128;

    const int r  = threadIdx.x >> 3;
    const int cc = (threadIdx.x & 7) * 16;
    const float* src = W + (size_t)(k0 + r) * HID + n0 + cc;
#pragma unroll
    for (int i = 0; i < 4; i++) {
        float4 f = *reinterpret_cast<const float4*>(src + i * 4);
        tile[r][cc + i * 4 + 0] = f.x;
        tile[r][cc + i * 4 + 1] = f.y;
        tile[r][cc + i * 4 + 2] = f.z;
        tile[r][cc + i * 4 + 3] = f.w;
    }
    __syncthreads();

    const int ch = threadIdx.x >> 1;
    const int sh = (threadIdx.x & 1) * 16;
    float v[16];
#pragma unroll
    for (int k = 0; k < 16; k++) v[k] = tile[sh + k][ch];

    size_t o = (size_t)(n0 + ch) * HID + k0 + sh;
    __nv_bfloat16 h[16];
#pragma unroll
    for (int k = 0; k < 16; k++) h[k] = __float2bfloat16_rn(v[k]);

    if (z == 0) {
        __nv_bfloat16 l[16];
#pragma unroll
        for (int k = 0; k < 16; k++)
            l[k] = __float2bfloat16_rn(v[k] - __bfloat162float(h[k]));
        *reinterpret_cast<uint4*>(g_Wkh + o)     = reinterpret_cast<uint4*>(h)[0];
        *reinterpret_cast<uint4*>(g_Wkh + o + 8) = reinterpret_cast<uint4*>(h)[1];
        *reinterpret_cast<uint4*>(g_Wkl + o)     = reinterpret_cast<uint4*>(l)[0];
        *reinterpret_cast<uint4*>(g_Wkl + o + 8) = reinterpret_cast<uint4*>(l)[1];
    } else {
        uint8_t h8[16], l8[16];
#pragma unroll
        for (int k = 0; k < 16; k++) {
            h8[k] = f2e4m3(v[k]);
            l8[k] = f2e4m3((v[k] - __bfloat162float(h[k])) * RSCALE);
        }
        if (z == 1) {
            *reinterpret_cast<uint4*>(g_Wvh + o)     = reinterpret_cast<uint4*>(h)[0];
            *reinterpret_cast<uint4*>(g_Wvh + o + 8) = reinterpret_cast<uint4*>(h)[1];
            *reinterpret_cast<uint4*>(g_Wv8h + o)    = *reinterpret_cast<uint4*>(h8);
            *reinterpret_cast<uint4*>(g_Wv8l + o)    = *reinterpret_cast<uint4*>(l8);
        } else {
            *reinterpret_cast<uint4*>(g_Woh + o)     = reinterpret_cast<uint4*>(h)[0];
            *reinterpret_cast<uint4*>(g_Woh + o + 8) = reinterpret_cast<uint4*>(h)[1];
            *reinterpret_cast<uint4*>(g_Wo8h + o)    = *reinterpret_cast<uint4*>(h8);
            *reinterpret_cast<uint4*>(g_Wo8l + o)    = *reinterpret_cast<uint4*>(l8);
        }
    }
}

// -------- E[n,a,b] = sum_{i,d} Wq[i, a*64+d] * T[n][i, b*64+d] --------------
__global__ __launch_bounds__(256)
void ereduce(const float* __restrict__ Wq)
{
    const int n  = blockIdx.x;
    const int i0 = blockIdx.y * 16;
    const int tid = threadIdx.x;
    const int a = tid & 15, b = tid >> 4;

    __shared__ float qs[4][1088];
    __shared__ float ks[4][1088];

    const float* Tb = g_T + (size_t)n * HID * HID;

    float acc = 0.0f;
    for (int batch = 0; batch < 4; batch++) {
        const int irow = i0 + batch * 4;
#pragma unroll
        for (int t = 0; t < 8; t++) {
            int f  = tid + t * 256;
            int ff = f & 1023;
            int rl = ff >> 8;
            int ch = ff & 255;
            const float* src = ((f < 1024) ? Wq : Tb) + (size_t)(irow + rl) * HID + ch * 4;
            float4 v = *reinterpret_cast<const float4*>(src);
            float* dst = (f < 1024) ? qs[rl] : ks[rl];
            int c = ch * 4, d0 = c & 63, h = c >> 6;
            dst[(d0 + 0) * 17 + h] = v.x;
            dst[(d0 + 1) * 17 + h] = v.y;
            dst[(d0 + 2) * 17 + h] = v.z;
            dst[(d0 + 3) * 17 + h] = v.w;
        }
        __syncthreads();
#pragma unroll
        for (int rl = 0; rl < 4; rl++)
#pragma unroll
            for (int d = 0; d < 64; d++)
                acc = fmaf(qs[rl][d * 17 + a], ks[rl][d * 17 + b], acc);
        __syncthreads();
    }
    atomicAdd(&g_E[n * 256 + a * 16 + b], acc);
}

// ---------------- softmax over b ------------------------------------------
__global__ void softmax_kernel()
{
    int t = threadIdx.x;
    if (t >= N_BATCH * NHEADS) return;
    int n = t >> 4, a = t & 15;
    const float* e = g_E + n * 256 + a * 16;
    float v[16], m = -1e30f;
#pragma unroll
    for (int b = 0; b < 16; b++) { v[b] = e[b] * 0.125f; m = fmaxf(m, v[b]); }
    float s = 0.0f;
#pragma unroll
    for (int b = 0; b < 16; b++) { v[b] = expf(v[b] - m); s += v[b]; }
    float inv = 1.0f / s;
    float* o = g_A + n * 256 + a * 16;
#pragma unroll
    for (int b = 0; b < 16; b++) o[b] = v[b] * inv;
}

// ---------------- launch ----------------------------------------------------
extern "C" void kernel_launch(void* const* d_in, const int* in_sizes, int n_in,
                              void* d_out, int out_size)
{
    const float* x  = (const float*)d_in[0];
    const float* Wq = (const float*)d_in[1];
    const float* Wk = (const float*)d_in[2];
    const float* Wv = (const float*)d_in[3];
    const float* Wo = (const float*)d_in[4];
    const float* bo = (const float*)d_in[5];
    float* out = (float*)d_out;

    float *pT, *pE, *pAtn;
    __nv_bfloat16 *pxh, *pxTh, *pxTl, *pGh, *pGl, *pAh;
    __nv_bfloat16 *pWkh, *pWkl, *pWvh, *pWoh;
    uint8_t *pxh8, *pxl8, *pA8h, *pA8l, *pWv8h, *pWv8l, *pWo8h, *pWo8l;
    cudaGetSymbolAddress((void**)&pT,  g_T);
    cudaGetSymbolAddress((void**)&pE,  g_E);
    cudaGetSymbolAddress((void**)&pAtn, g_A);
    cudaGetSymbolAddress((void**)&pxh, g_xh);
    cudaGetSymbolAddress((void**)&pxh8, g_xh8);
    cudaGetSymbolAddress((void**)&pxl8, g_xl8);
    cudaGetSymbolAddress((void**)&pxTh, g_xTh);
    cudaGetSymbolAddress((void**)&pxTl, g_xTl);
    cudaGetSymbolAddress((void**)&pGh, g_Gh);
    cudaGetSymbolAddress((void**)&pGl, g_Gl);
    cudaGetSymbolAddress((void**)&pAh, g_Ah);
    cudaGetSymbolAddress((void**)&pA8h, g_A8h);
    cudaGetSymbolAddress((void**)&pA8l, g_A8l);
    cudaGetSymbolAddress((void**)&pWkh, g_Wkh);
    cudaGetSymbolAddress((void**)&pWkl, g_Wkl);
    cudaGetSymbolAddress((void**)&pWvh, g_Wvh);
    cudaGetSymbolAddress((void**)&pWoh, g_Woh);
    cudaGetSymbolAddress((void**)&pWv8h, g_Wv8h);
    cudaGetSymbolAddress((void**)&pWv8l, g_Wv8l);
    cudaGetSymbolAddress((void**)&pWo8h, g_Wo8h);
    cudaGetSymbolAddress((void**)&pWo8l, g_Wo8l);

    cudaFuncSetAttribute(gemm3, cudaFuncAttributeMaxDynamicSharedMemorySize, GEMM3_SMEM);
    cudaFuncSetAttribute(gemm_mixed, cudaFuncAttributeMaxDynamicSharedMemorySize, GEMM_SMEM);

    convert_x<<<dim3(HID / 128, SEQ / 32, N_BATCH), 256>>>(x);
    convert_w<<<dim3(HID / 128, HID / 32, 3), 256>>>(Wk, Wv, Wo);

    // Gram: G[n] = x[n]^T x[n]
    gemm3<<<dim3(8, 8, N_BATCH), 256, GEMM3_SMEM>>>(
        pxTh, pxTl, pxTh, pxTl, SEQ, SEQ, SEQ,
        (size_t)HID * SEQ, (size_t)HID * SEQ, (size_t)HID * HID,
        nullptr, pGh, pGl, HID, 1, 1);

    // T[n] = G[n] @ Wk
    gemm3<<<dim3(8, 8, N_BATCH), 256, GEMM3_SMEM>>>(
        pGh, pGl, pWkh, pWkl, HID, HID, HID,
        (size_t)HID * HID, 0, (size_t)HID * HID,
        pT, nullptr, nullptr, HID, 0, 0);

    cudaMemsetAsync(pE, 0, N_BATCH * NHEADS * NHEADS * sizeof(float), 0);
    ereduce<<<dim3(N_BATCH, HID / 16), 256>>>(Wq);
    softmax_kernel<<<1, 64>>>();

    // V = x @ Wv, epilogue writes permuted split operand A
    gemm_mixed<<<dim3(HID / 128, MROWS / 128), 256, GEMM_SMEM>>>(
        pxh, pxh8, pxl8, pWvh, pWv8h, pWv8l, nullptr, nullptr,
        nullptr, pAh, pA8h, pA8l, 1);

    // out = attn-mix(A @ Wo) + bo, fused epilogue
    gemm_mixed<<<dim3(HID / 128, MROWS / 128), 256, GEMM_SMEM>>>(
        pAh, pA8h, pA8l, pWoh, pWo8h, pWo8l, bo, pAtn,
        out, nullptr, nullptr, nullptr, 2);
}